// round 10
// baseline (speedup 1.0000x reference)
#include <cuda_runtime.h>
#include <cuda_bf16.h>
#include <cuda_fp16.h>
#include <cstddef>
#include <cstdint>

// ---------------------------------------------------------------------------
// GNN: relu(x@W_in+b); 2x SAGEConv(mean) + BN(eval) + relu; out GEMM.
// N=100000, E=1.6M, D_IN=256, H=128, D_OUT=64, fp32 in/out.
//
// R9: activations flow between kernels as PRE-SPLIT bf16 hi/lo planes
// (producer-side split). Consumer GEMMs are pure cp.async pipelines (no
// split8 / register staging in-loop). Input GEMM keeps the R8 fp32 path.
// Gather reads fp16 copy, writes hi/lo planes. Same numerics as R8.
// ---------------------------------------------------------------------------

#define MAX_N 100000
#define MAX_E 1600000
#define HID   128

// bf16 activation planes (hi/lo)
__device__ __nv_bfloat16 g_ah[(size_t)MAX_N * HID];
__device__ __nv_bfloat16 g_al[(size_t)MAX_N * HID];
__device__ __nv_bfloat16 g_bh[(size_t)MAX_N * HID];
__device__ __nv_bfloat16 g_bl[(size_t)MAX_N * HID];
__device__ __nv_bfloat16 g_gh[(size_t)MAX_N * HID];
__device__ __nv_bfloat16 g_gl[(size_t)MAX_N * HID];
__device__ __half g_h16 [(size_t)MAX_N * HID];
__device__ float  g_rdeg[MAX_N];
__device__ int    g_degi  [MAX_N];
__device__ int    g_cursor[MAX_N];
__device__ int    g_rowptr[MAX_N + 1];
__device__ int    g_csr   [MAX_E];
__device__ int    g_bsum  [1024];
__device__ __nv_bfloat16 g_wth[4][128 * 256];
__device__ __nv_bfloat16 g_wtl[4][128 * 256];

// ---------------------------------------------------------------------------
// helpers
// ---------------------------------------------------------------------------
__device__ __forceinline__ uint32_t smem_u32(const void* p) {
    uint32_t a;
    asm("{ .reg .u64 t; cvta.to.shared.u64 t, %1; cvt.u32.u64 %0, t; }"
        : "=r"(a) : "l"(p));
    return a;
}

__device__ __forceinline__ void ldsm_x4(uint32_t* r, uint32_t addr) {
    asm volatile("ldmatrix.sync.aligned.m8n8.x4.shared.b16 {%0,%1,%2,%3}, [%4];"
                 : "=r"(r[0]), "=r"(r[1]), "=r"(r[2]), "=r"(r[3]) : "r"(addr));
}

__device__ __forceinline__ void mma_bf16(float* c, const uint32_t* a, const uint32_t* b) {
    asm volatile("mma.sync.aligned.m16n8k16.row.col.f32.bf16.bf16.f32 "
                 "{%0,%1,%2,%3}, {%4,%5,%6,%7}, {%8,%9}, {%0,%1,%2,%3};"
                 : "+f"(c[0]), "+f"(c[1]), "+f"(c[2]), "+f"(c[3])
                 : "r"(a[0]), "r"(a[1]), "r"(a[2]), "r"(a[3]),
                   "r"(b[0]), "r"(b[1]));
}

__device__ __forceinline__ void cp16(uint32_t saddr, const void* gptr) {
    asm volatile("cp.async.ca.shared.global [%0], [%1], 16;"
                 :: "r"(saddr), "l"(gptr) : "memory");
}
__device__ __forceinline__ void cp16z(uint32_t saddr, const void* gptr, bool valid) {
    int sz = valid ? 16 : 0;
    asm volatile("cp.async.ca.shared.global [%0], [%1], 16, %2;"
                 :: "r"(saddr), "l"(gptr), "r"(sz) : "memory");
}
__device__ __forceinline__ void cp_commit() {
    asm volatile("cp.async.commit_group;" ::: "memory");
}
template<int NN>
__device__ __forceinline__ void cp_wait() {
    asm volatile("cp.async.wait_group %0;" :: "n"(NN) : "memory");
}

__device__ __forceinline__ uint32_t pack2(float a, float b) {
    __nv_bfloat162 t = __floats2bfloat162_rn(a, b);
    return *reinterpret_cast<uint32_t*>(&t);
}

__device__ __forceinline__ void split8(const float4& v0, const float4& v1,
                                       uint4& hi, uint4& lo) {
    float f[8] = {v0.x, v0.y, v0.z, v0.w, v1.x, v1.y, v1.z, v1.w};
    float h[8], l[8];
#pragma unroll
    for (int i = 0; i < 8; ++i) {
        __nv_bfloat16 hb = __float2bfloat16_rn(f[i]);
        float hf = __bfloat162float(hb);
        h[i] = hf;
        l[i] = f[i] - hf;
    }
    hi.x = pack2(h[0], h[1]); hi.y = pack2(h[2], h[3]);
    hi.z = pack2(h[4], h[5]); hi.w = pack2(h[6], h[7]);
    lo.x = pack2(l[0], l[1]); lo.y = pack2(l[2], l[3]);
    lo.z = pack2(l[4], l[5]); lo.w = pack2(l[6], l[7]);
}

// ---------------------------------------------------------------------------
// CSR build (unchanged)
// ---------------------------------------------------------------------------
__global__ void zero_int_kernel(int* __restrict__ a, int* __restrict__ b, int n) {
    int i = blockIdx.x * blockDim.x + threadIdx.x;
    if (i < n) { a[i] = 0; b[i] = 0; }
}

__global__ void degi_kernel(const int* __restrict__ dst, int* __restrict__ deg, int E) {
    int e = blockIdx.x * blockDim.x + threadIdx.x;
    if (e < E) atomicAdd(&deg[dst[e]], 1);
}

__global__ void rdeg_kernel(const int* __restrict__ deg, float* __restrict__ rdeg, int n) {
    int i = blockIdx.x * blockDim.x + threadIdx.x;
    if (i < n) rdeg[i] = 1.0f / fmaxf((float)deg[i], 1.0f);
}

__global__ void scan1_kernel(const int* __restrict__ deg, int* __restrict__ rowptr,
                             int* __restrict__ bsum, int n) {
    __shared__ int warp_tot[8];
    int t = threadIdx.x, lane = t & 31, wid = t >> 5;
    int base = blockIdx.x * 1024 + t * 4;
    int v0 = (base + 0 < n) ? deg[base + 0] : 0;
    int v1 = (base + 1 < n) ? deg[base + 1] : 0;
    int v2 = (base + 2 < n) ? deg[base + 2] : 0;
    int v3 = (base + 3 < n) ? deg[base + 3] : 0;
    int tot = v0 + v1 + v2 + v3;

    int inc = tot;
#pragma unroll
    for (int off = 1; off < 32; off <<= 1) {
        int y = __shfl_up_sync(0xFFFFFFFF, inc, off);
        if (lane >= off) inc += y;
    }
    if (lane == 31) warp_tot[wid] = inc;
    __syncthreads();
    if (wid == 0) {
        int w = (lane < 8) ? warp_tot[lane] : 0;
        int wi = w;
#pragma unroll
        for (int off = 1; off < 8; off <<= 1) {
            int y = __shfl_up_sync(0xFFFFFFFF, wi, off);
            if (lane >= off) wi += y;
        }
        if (lane < 8) warp_tot[lane] = wi - w;
    }
    __syncthreads();
    int excl = warp_tot[wid] + inc - tot;

    if (base + 0 < n) rowptr[base + 0] = excl;
    if (base + 1 < n) rowptr[base + 1] = excl + v0;
    if (base + 2 < n) rowptr[base + 2] = excl + v0 + v1;
    if (base + 3 < n) rowptr[base + 3] = excl + v0 + v1 + v2;
    if (t == 255) bsum[blockIdx.x] = warp_tot[7] + inc;
}

__global__ void scan2_kernel(int* __restrict__ bsum, int nblk) {
    __shared__ int sh[1024];
    int t = threadIdx.x;
#pragma unroll
    for (int i = 0; i < 4; ++i) {
        int idx = t + i * 256;
        sh[idx] = (idx < nblk) ? bsum[idx] : 0;
    }
    __syncthreads();
    for (int off = 1; off < 1024; off <<= 1) {
        int v[4];
#pragma unroll
        for (int i = 0; i < 4; ++i) {
            int idx = t + i * 256;
            v[i] = (idx >= off) ? sh[idx - off] : 0;
        }
        __syncthreads();
#pragma unroll
        for (int i = 0; i < 4; ++i) sh[t + i * 256] += v[i];
        __syncthreads();
    }
#pragma unroll
    for (int i = 0; i < 4; ++i) {
        int idx = t + i * 256;
        if (idx < nblk) bsum[idx] = (idx == 0) ? 0 : sh[idx - 1];
    }
}

__global__ void scan3_kernel(int* __restrict__ rowptr, const int* __restrict__ bsum,
                             int n, int E) {
    int i = blockIdx.x * blockDim.x + threadIdx.x;
    if (i < n) rowptr[i] += bsum[i >> 10];
    if (i == 0) rowptr[n] = E;
}

__global__ void fill_kernel(const int* __restrict__ src, const int* __restrict__ dst,
                            const int* __restrict__ rowptr, int* __restrict__ cursor,
                            int* __restrict__ csr, int E) {
    int e = blockIdx.x * blockDim.x + threadIdx.x;
    if (e >= E) return;
    int d = dst[e];
    int pos = rowptr[d] + atomicAdd(&cursor[d], 1);
    csr[pos] = src[e];
}

// ---------------------------------------------------------------------------
// Gather (fp16 in -> bf16 hi/lo planes out). Warp per node, mean fused.
// ---------------------------------------------------------------------------
__global__ void __launch_bounds__(256)
gather_kernel(const uint2* __restrict__ h2, const int* __restrict__ rowptr,
              const int* __restrict__ csr, const float* __restrict__ rdeg,
              __nv_bfloat16* __restrict__ GH, __nv_bfloat16* __restrict__ GL,
              int n) {
    int gw   = (blockIdx.x * blockDim.x + threadIdx.x) >> 5;
    int lane = threadIdx.x & 31;
    if (gw >= n) return;
    int s0 = rowptr[gw], s1 = rowptr[gw + 1];
    float ax = 0.f, ay = 0.f, az = 0.f, aw = 0.f;
    int j = s0;
    for (; j + 4 <= s1; j += 4) {
        int i0 = __ldg(&csr[j]);
        int i1 = __ldg(&csr[j + 1]);
        int i2 = __ldg(&csr[j + 2]);
        int i3 = __ldg(&csr[j + 3]);
        uint2 u0 = h2[(size_t)i0 * 32 + lane];
        uint2 u1 = h2[(size_t)i1 * 32 + lane];
        uint2 u2 = h2[(size_t)i2 * 32 + lane];
        uint2 u3 = h2[(size_t)i3 * 32 + lane];
#pragma unroll
        for (int q = 0; q < 4; ++q) {
            uint2 u = (q == 0) ? u0 : (q == 1) ? u1 : (q == 2) ? u2 : u3;
            float2 p0 = __half22float2(*reinterpret_cast<__half2*>(&u.x));
            float2 p1 = __half22float2(*reinterpret_cast<__half2*>(&u.y));
            ax += p0.x; ay += p0.y; az += p1.x; aw += p1.y;
        }
    }
    for (; j < s1; ++j) {
        int i0 = __ldg(&csr[j]);
        uint2 u = h2[(size_t)i0 * 32 + lane];
        float2 p0 = __half22float2(*reinterpret_cast<__half2*>(&u.x));
        float2 p1 = __half22float2(*reinterpret_cast<__half2*>(&u.y));
        ax += p0.x; ay += p0.y; az += p1.x; aw += p1.y;
    }
    float rd = rdeg[gw];
    float m[4] = {ax * rd, ay * rd, az * rd, aw * rd};
    float h[4], l[4];
#pragma unroll
    for (int q = 0; q < 4; ++q) {
        __nv_bfloat16 hb = __float2bfloat16_rn(m[q]);
        h[q] = __bfloat162float(hb);
        l[q] = m[q] - h[q];
    }
    uint2 hv = make_uint2(pack2(h[0], h[1]), pack2(h[2], h[3]));
    uint2 lv = make_uint2(pack2(l[0], l[1]), pack2(l[2], l[3]));
    *(uint2*)(GH + (size_t)gw * HID + lane * 4) = hv;
    *(uint2*)(GL + (size_t)gw * HID + lane * 4) = lv;
}

// ---------------------------------------------------------------------------
// Weight prep: transpose + bf16 hi/lo split.  out[n*Ktot+k] = W[k,n]
// ---------------------------------------------------------------------------
__global__ void wprep_kernel(const float* __restrict__ W0, const float* __restrict__ W1,
                             int K0, int Ktot, int BNw,
                             __nv_bfloat16* __restrict__ oh,
                             __nv_bfloat16* __restrict__ ol) {
    int i = blockIdx.x * blockDim.x + threadIdx.x;
    if (i >= BNw * Ktot) return;
    int n = i / Ktot, k = i % Ktot;
    float w = (k < K0) ? W0[(size_t)k * BNw + n] : W1[(size_t)(k - K0) * BNw + n];
    __nv_bfloat16 h = __float2bfloat16_rn(w);
    oh[i] = h;
    ol[i] = __float2bfloat16_rn(w - __bfloat162float(h));
}

// ---------------------------------------------------------------------------
// HMMA split-bf16 GEMM.
//  PRESPLIT=false: A fp32 (X, stride sX), R8 reg-staged split path.
//  PRESPLIT=true : A from bf16 hi/lo planes, pure cp.async pipeline.
//  OUTSPLIT: write bf16 hi/lo planes (OH/OL); else fp32 C. WH: + fp16 copy.
// Block 128 x BN, 8 warps (4x2), warp tile 32 x BN/2, pitch-80 smem.
// ---------------------------------------------------------------------------
template<int BN, int NC, int NC0, bool RELU, bool AFF, bool WH,
         bool PRESPLIT, bool OUTSPLIT>
__global__ void __launch_bounds__(256, 2)
mma_gemm_kernel(const float* __restrict__ X, int sX,
                const __nv_bfloat16* __restrict__ Ah0,
                const __nv_bfloat16* __restrict__ Al0, int sA0,
                const __nv_bfloat16* __restrict__ Ah1,
                const __nv_bfloat16* __restrict__ Al1, int sA1,
                const __nv_bfloat16* __restrict__ Wh,
                const __nv_bfloat16* __restrict__ Wl,
                const float* __restrict__ bias,
                const float* __restrict__ gamma,
                const float* __restrict__ beta,
                float* __restrict__ C,
                __nv_bfloat16* __restrict__ OH,
                __nv_bfloat16* __restrict__ OL,
                __half* __restrict__ H16, int Nrows)
{
    constexpr int KTOT   = NC * 32;
    constexpr int WN     = BN / 2;
    constexpr int NT8    = WN / 8;
    constexpr int NT16   = WN / 16;
    constexpr int APITCH = 80;
    constexpr int ABYTES = 128 * APITCH;
    constexpr int BBYTES = BN * APITCH;
    constexpr int STAGE  = 2 * ABYTES + 2 * BBYTES;
    constexpr int BPER   = (BN * 4) / 256;

    extern __shared__ __align__(128) char smem[];
    const uint32_t sbase = smem_u32(smem);

    const int tid  = threadIdx.x;
    const int wid  = tid >> 5;
    const int lane = tid & 31;
    const int wm   = wid & 3;
    const int wn   = wid >> 2;
    const int row0 = blockIdx.x * 128;

    float acc[2][NT8][4];
#pragma unroll
    for (int mt = 0; mt < 2; ++mt)
#pragma unroll
        for (int nt = 0; nt < NT8; ++nt)
#pragma unroll
            for (int q = 0; q < 4; ++q) acc[mt][nt][q] = 0.0f;

    float4 af[2][2];   // only used when !PRESPLIT

    auto load_tileA_f32 = [&](int c) {
#pragma unroll
        for (int s = 0; s < 2; ++s) {
            int f = tid + s * 256;
            int r = f >> 2, seg = f & 3;
            float4 v0 = make_float4(0.f, 0.f, 0.f, 0.f), v1 = v0;
            int grow = row0 + r;
            if (grow < Nrows) {
                const float* p = X + (size_t)grow * sX + c * 32 + seg * 8;
                v0 = *(const float4*)p;
                v1 = *(const float4*)(p + 4);
            }
            af[s][0] = v0; af[s][1] = v1;
        }
    };

    auto store_tileA_f32 = [&](int buf) {
        char* sp = smem + buf * STAGE;
#pragma unroll
        for (int s = 0; s < 2; ++s) {
            int f = tid + s * 256;
            int r = f >> 2, seg = f & 3;
            uint4 hi, lo;
            split8(af[s][0], af[s][1], hi, lo);
            uint32_t off = (uint32_t)(r * APITCH + seg * 16);
            *(uint4*)(sp + off)          = hi;
            *(uint4*)(sp + ABYTES + off) = lo;
        }
    };

    auto loadA_async = [&](int c, int buf) {
        const __nv_bfloat16 *Hp, *Lp; int stride, koff;
        if (c < NC0) { Hp = Ah0; Lp = Al0; stride = sA0; koff = c * 32; }
        else         { Hp = Ah1; Lp = Al1; stride = sA1; koff = (c - NC0) * 32; }
        const uint32_t abase = sbase + buf * STAGE;
#pragma unroll
        for (int s = 0; s < 2; ++s) {
            int f = tid + s * 256;
            int r = f >> 2, seg = f & 3;
            int grow = row0 + r;
            bool ok = grow < Nrows;
            size_t g = (size_t)(ok ? grow : 0) * stride + koff + seg * 8;
            uint32_t off = (uint32_t)(r * APITCH + seg * 16);
            cp16z(abase + off,          Hp + g, ok);
            cp16z(abase + ABYTES + off, Lp + g, ok);
        }
    };

    auto loadB_async = [&](int c, int buf) {
        const uint32_t bbase = sbase + buf * STAGE + 2 * ABYTES;
#pragma unroll
        for (int s = 0; s < BPER; ++s) {
            int f = tid + s * 256;
            int n = f >> 2, seg = f & 3;
            size_t g = (size_t)n * KTOT + c * 32 + seg * 8;
            uint32_t off = (uint32_t)(n * APITCH + seg * 16);
            cp16(bbase + off,          Wh + g);
            cp16(bbase + BBYTES + off, Wl + g);
        }
    };

    auto compute = [&](int buf) {
        const uint32_t aAh = sbase + buf * STAGE;
        const uint32_t aAl = aAh + ABYTES;
        const uint32_t aBh = aAh + 2 * ABYTES;
        const uint32_t aBl = aBh + BBYTES;
#pragma unroll
        for (int ks = 0; ks < 2; ++ks) {
            uint32_t ah[2][4], al[2][4];
#pragma unroll
            for (int mt = 0; mt < 2; ++mt) {
                uint32_t off = (uint32_t)((wm * 32 + mt * 16 + (lane & 15)) * APITCH
                                          + (ks * 16 + (lane >> 4) * 8) * 2);
                ldsm_x4(ah[mt], aAh + off);
                ldsm_x4(al[mt], aAl + off);
            }
#pragma unroll
            for (int nt2 = 0; nt2 < NT16; ++nt2) {
                uint32_t off = (uint32_t)((wn * WN + nt2 * 16 + (lane & 7)
                                           + ((lane >> 4) & 1) * 8) * APITCH
                                          + (ks * 16 + ((lane >> 3) & 1) * 8) * 2);
                uint32_t bh[4], bl[4];
                ldsm_x4(bh, aBh + off);
                ldsm_x4(bl, aBl + off);
#pragma unroll
                for (int mt = 0; mt < 2; ++mt) {
                    mma_bf16(acc[mt][nt2 * 2 + 0], ah[mt], bh + 0);
                    mma_bf16(acc[mt][nt2 * 2 + 0], ah[mt], bl + 0);
                    mma_bf16(acc[mt][nt2 * 2 + 0], al[mt], bh + 0);
                    mma_bf16(acc[mt][nt2 * 2 + 1], ah[mt], bh + 2);
                    mma_bf16(acc[mt][nt2 * 2 + 1], ah[mt], bl + 2);
                    mma_bf16(acc[mt][nt2 * 2 + 1], al[mt], bh + 2);
                }
            }
        }
    };

    if constexpr (PRESPLIT) {
        loadA_async(0, 0);
        loadB_async(0, 0);
        cp_commit();
#pragma unroll
        for (int c = 0; c < NC; ++c) {
            if (c + 1 < NC) {
                loadA_async(c + 1, (c + 1) & 1);
                loadB_async(c + 1, (c + 1) & 1);
                cp_commit();
                cp_wait<1>();
            } else {
                cp_wait<0>();
            }
            __syncthreads();
            compute(c & 1);
            __syncthreads();
        }
    } else {
        loadB_async(0, 0);
        cp_commit();
        load_tileA_f32(0);
        store_tileA_f32(0);
        cp_wait<0>();
        __syncthreads();
#pragma unroll
        for (int c = 0; c < NC; ++c) {
            if (c + 1 < NC) {
                loadB_async(c + 1, (c + 1) & 1);
                cp_commit();
                load_tileA_f32(c + 1);
            }
            compute(c & 1);
            if (c + 1 < NC) store_tileA_f32((c + 1) & 1);
            cp_wait<0>();
            __syncthreads();
        }
    }

    // ---- epilogue ----
    const int cb = wn * WN + 2 * (lane & 3);
    float2 scv[NT8], shv[NT8];
#pragma unroll
    for (int nt = 0; nt < NT8; ++nt) {
        int col = cb + nt * 8;
        float s0, h0, s1, h1;
        if constexpr (AFF) {
            s0 = __ldg(&gamma[col])     * rsqrtf(1.0f + 1e-5f);
            s1 = __ldg(&gamma[col + 1]) * rsqrtf(1.0f + 1e-5f);
            h0 = s0 * __ldg(&bias[col])     + __ldg(&beta[col]);
            h1 = s1 * __ldg(&bias[col + 1]) + __ldg(&beta[col + 1]);
        } else {
            s0 = 1.0f; s1 = 1.0f;
            h0 = __ldg(&bias[col]);
            h1 = __ldg(&bias[col + 1]);
        }
        scv[nt] = make_float2(s0, s1);
        shv[nt] = make_float2(h0, h1);
    }
    const int rbase = row0 + wm * 32 + (lane >> 2);
#pragma unroll
    for (int mt = 0; mt < 2; ++mt) {
#pragma unroll
        for (int h = 0; h < 2; ++h) {
            int row = rbase + mt * 16 + h * 8;
            if (row >= Nrows) continue;
#pragma unroll
            for (int nt = 0; nt < NT8; ++nt) {
                float v0 = acc[mt][nt][h * 2 + 0] * scv[nt].x + shv[nt].x;
                float v1 = acc[mt][nt][h * 2 + 1] * scv[nt].y + shv[nt].y;
                if constexpr (RELU) { v0 = fmaxf(v0, 0.0f); v1 = fmaxf(v1, 0.0f); }
                size_t base = (size_t)row * BN + cb + nt * 8;
                if constexpr (OUTSPLIT) {
                    __nv_bfloat16 h0 = __float2bfloat16_rn(v0);
                    __nv_bfloat16 h1 = __float2bfloat16_rn(v1);
                    float l0 = v0 - __bfloat162float(h0);
                    float l1 = v1 - __bfloat162float(h1);
                    *(uint32_t*)(OH + base) = pack2(__bfloat162float(h0), __bfloat162float(h1));
                    *(uint32_t*)(OL + base) = pack2(l0, l1);
                } else {
                    *(float2*)(C + base) = make_float2(v0, v1);
                }
                if constexpr (WH)
                    *(__half2*)(H16 + base) = __floats2half2_rn(v0, v1);
            }
        }
    }
}

// ---------------------------------------------------------------------------
// Host launcher
// ---------------------------------------------------------------------------
extern "C" void kernel_launch(void* const* d_in, const int* in_sizes, int n_in,
                              void* d_out, int out_size)
{
    const float* x     = (const float*)d_in[0];
    const int*   eidx  = (const int*)  d_in[1];
    const float* w_in  = (const float*)d_in[2];
    const float* b_in  = (const float*)d_in[3];
    const float* w_l1  = (const float*)d_in[4];
    const float* b_l1  = (const float*)d_in[5];
    const float* w_r1  = (const float*)d_in[6];
    const float* g1    = (const float*)d_in[7];
    const float* be1   = (const float*)d_in[8];
    const float* w_l2  = (const float*)d_in[9];
    const float* b_l2  = (const float*)d_in[10];
    const float* w_r2  = (const float*)d_in[11];
    const float* g2    = (const float*)d_in[12];
    const float* be2   = (const float*)d_in[13];
    const float* w_out = (const float*)d_in[14];
    const float* b_out = (const float*)d_in[15];
    float* out = (float*)d_out;

    const int N = in_sizes[0] / 256;
    const int E = in_sizes[1] / 2;
    const int* src = eidx;
    const int* dst = eidx + E;

    __nv_bfloat16 *ah, *al, *bh, *bl, *gh, *gl, *wth, *wtl;
    __half* h16;
    float* rdeg;
    int *degi, *cursor, *rowptr, *csr, *bsum;
    cudaGetSymbolAddress((void**)&ah,     g_ah);
    cudaGetSymbolAddress((void**)&al,     g_al);
    cudaGetSymbolAddress((void**)&bh,     g_bh);
    cudaGetSymbolAddress((void**)&bl,     g_bl);
    cudaGetSymbolAddress((void**)&gh,     g_gh);
    cudaGetSymbolAddress((void**)&gl,     g_gl);
    cudaGetSymbolAddress((void**)&h16,    g_h16);
    cudaGetSymbolAddress((void**)&rdeg,   g_rdeg);
    cudaGetSymbolAddress((void**)&degi,   g_degi);
    cudaGetSymbolAddress((void**)&cursor, g_cursor);
    cudaGetSymbolAddress((void**)&rowptr, g_rowptr);
    cudaGetSymbolAddress((void**)&csr,    g_csr);
    cudaGetSymbolAddress((void**)&bsum,   g_bsum);
    cudaGetSymbolAddress((void**)&wth,    g_wth);
    cudaGetSymbolAddress((void**)&wtl,    g_wtl);
    const int WSTR = 128 * 256;

    const int nBlocks    = (N + 255) / 256;
    const int eBlocks    = (E + 255) / 256;
    const int gemmBlocks = (N + 127) / 128;
    const int scanBlocks = (N + 1023) / 1024;
    const int gatherBlocks = (int)(((long long)N * 32 + 255) / 256);

    const int S128 = 2 * (2 * 128 * 80 + 2 * 128 * 80);   // 81920
    const int S64  = 2 * (2 * 128 * 80 + 2 * 64 * 80);    // 61440
    cudaFuncSetAttribute(mma_gemm_kernel<128, 8, 8, true,  false, true,  false, true >,
                         cudaFuncAttributeMaxDynamicSharedMemorySize, S128);
    cudaFuncSetAttribute(mma_gemm_kernel<128, 8, 4, true,  true,  true,  true,  true >,
                         cudaFuncAttributeMaxDynamicSharedMemorySize, S128);
    cudaFuncSetAttribute(mma_gemm_kernel<128, 8, 4, true,  true,  false, true,  true >,
                         cudaFuncAttributeMaxDynamicSharedMemorySize, S128);
    cudaFuncSetAttribute(mma_gemm_kernel<64,  4, 4, false, false, false, true,  false>,
                         cudaFuncAttributeMaxDynamicSharedMemorySize, S64);

    // launch order: input GEMM in ncu's capture slot (4th)
    zero_int_kernel<<<nBlocks, 256>>>(degi, cursor, N);                      // 1
    degi_kernel<<<eBlocks, 256>>>(dst, degi, E);                             // 2
    wprep_kernel<<<(128 * 256 + 255) / 256, 256>>>(w_in, nullptr, 256, 256, 128,
                                                   wth + 0 * WSTR, wtl + 0 * WSTR); // 3
    // input layer: (ah, al, h16) = relu(x @ w_in + b_in)
    mma_gemm_kernel<128, 8, 8, true, false, true, false, true>
        <<<gemmBlocks, 256, S128>>>(
        x, 256, nullptr, nullptr, 0, nullptr, nullptr, 0,
        wth + 0 * WSTR, wtl + 0 * WSTR,
        b_in, nullptr, nullptr, nullptr, ah, al, h16, N);                    // 4 <- profiled

    rdeg_kernel<<<nBlocks, 256>>>(degi, rdeg, N);
    scan1_kernel<<<scanBlocks, 256>>>(degi, rowptr, bsum, N);
    scan2_kernel<<<1, 256>>>(bsum, scanBlocks);
    scan3_kernel<<<nBlocks, 256>>>(rowptr, bsum, N, E);
    fill_kernel<<<eBlocks, 256>>>(src, dst, rowptr, cursor, csr, E);

    wprep_kernel<<<(128 * 256 + 255) / 256, 256>>>(w_l1, w_r1, 128, 256, 128,
                                                   wth + 1 * WSTR, wtl + 1 * WSTR);
    wprep_kernel<<<(128 * 256 + 255) / 256, 256>>>(w_l2, w_r2, 128, 256, 128,
                                                   wth + 2 * WSTR, wtl + 2 * WSTR);
    wprep_kernel<<<(64 * 128 + 255) / 256, 256>>>(w_out, nullptr, 128, 128, 64,
                                                  wth + 3 * WSTR, wtl + 3 * WSTR);

    // ---- SAGE layer 1 ----
    gather_kernel<<<gatherBlocks, 256>>>((const uint2*)h16, rowptr, csr, rdeg,
                                         gh, gl, N);
    mma_gemm_kernel<128, 8, 4, true, true, true, true, true>
        <<<gemmBlocks, 256, S128>>>(
        nullptr, 0, gh, gl, 128, ah, al, 128,
        wth + 1 * WSTR, wtl + 1 * WSTR,
        b_l1, g1, be1, nullptr, bh, bl, h16, N);

    // ---- SAGE layer 2 ----
    gather_kernel<<<gatherBlocks, 256>>>((const uint2*)h16, rowptr, csr, rdeg,
                                         gh, gl, N);
    mma_gemm_kernel<128, 8, 4, true, true, false, true, true>
        <<<gemmBlocks, 256, S128>>>(
        nullptr, 0, gh, gl, 128, bh, bl, 128,
        wth + 2 * WSTR, wtl + 2 * WSTR,
        b_l2, g2, be2, nullptr, ah, al, nullptr, N);

    // ---- output layer ----
    mma_gemm_kernel<64, 4, 4, false, false, false, true, false>
        <<<gemmBlocks, 256, S64>>>(
        nullptr, 0, ah, al, 128, nullptr, nullptr, 0,
        wth + 3 * WSTR, wtl + 3 * WSTR,
        b_out, nullptr, nullptr, out, nullptr, nullptr, nullptr, N);
}

// round 11
// speedup vs baseline: 1.0101x; 1.0101x over previous
#include <cuda_runtime.h>
#include <cuda_bf16.h>
#include <cuda_fp16.h>
#include <cstddef>
#include <cstdint>

// ---------------------------------------------------------------------------
// GNN: relu(x@W_in+b); 2x SAGEConv(mean) + BN(eval) + relu; out GEMM.
// N=100000, E=1.6M, D_IN=256, H=128, D_OUT=64, fp32 in/out.
//
// R10: PRESPLIT GEMM pipeline fixed to ONE barrier per chunk (loads for the
// next chunk issued before compute, waited after). Gather inner loop
// unrolled to 8 edges (2x MLP). Numerics identical to R9.
// ---------------------------------------------------------------------------

#define MAX_N 100000
#define MAX_E 1600000
#define HID   128

__device__ __nv_bfloat16 g_ah[(size_t)MAX_N * HID];
__device__ __nv_bfloat16 g_al[(size_t)MAX_N * HID];
__device__ __nv_bfloat16 g_bh[(size_t)MAX_N * HID];
__device__ __nv_bfloat16 g_bl[(size_t)MAX_N * HID];
__device__ __nv_bfloat16 g_gh[(size_t)MAX_N * HID];
__device__ __nv_bfloat16 g_gl[(size_t)MAX_N * HID];
__device__ __half g_h16 [(size_t)MAX_N * HID];
__device__ float  g_rdeg[MAX_N];
__device__ int    g_degi  [MAX_N];
__device__ int    g_cursor[MAX_N];
__device__ int    g_rowptr[MAX_N + 1];
__device__ int    g_csr   [MAX_E];
__device__ int    g_bsum  [1024];
__device__ __nv_bfloat16 g_wth[4][128 * 256];
__device__ __nv_bfloat16 g_wtl[4][128 * 256];

// ---------------------------------------------------------------------------
// helpers
// ---------------------------------------------------------------------------
__device__ __forceinline__ uint32_t smem_u32(const void* p) {
    uint32_t a;
    asm("{ .reg .u64 t; cvta.to.shared.u64 t, %1; cvt.u32.u64 %0, t; }"
        : "=r"(a) : "l"(p));
    return a;
}

__device__ __forceinline__ void ldsm_x4(uint32_t* r, uint32_t addr) {
    asm volatile("ldmatrix.sync.aligned.m8n8.x4.shared.b16 {%0,%1,%2,%3}, [%4];"
                 : "=r"(r[0]), "=r"(r[1]), "=r"(r[2]), "=r"(r[3]) : "r"(addr));
}

__device__ __forceinline__ void mma_bf16(float* c, const uint32_t* a, const uint32_t* b) {
    asm volatile("mma.sync.aligned.m16n8k16.row.col.f32.bf16.bf16.f32 "
                 "{%0,%1,%2,%3}, {%4,%5,%6,%7}, {%8,%9}, {%0,%1,%2,%3};"
                 : "+f"(c[0]), "+f"(c[1]), "+f"(c[2]), "+f"(c[3])
                 : "r"(a[0]), "r"(a[1]), "r"(a[2]), "r"(a[3]),
                   "r"(b[0]), "r"(b[1]));
}

__device__ __forceinline__ void cp16(uint32_t saddr, const void* gptr) {
    asm volatile("cp.async.ca.shared.global [%0], [%1], 16;"
                 :: "r"(saddr), "l"(gptr) : "memory");
}
__device__ __forceinline__ void cp16z(uint32_t saddr, const void* gptr, bool valid) {
    int sz = valid ? 16 : 0;
    asm volatile("cp.async.ca.shared.global [%0], [%1], 16, %2;"
                 :: "r"(saddr), "l"(gptr), "r"(sz) : "memory");
}
__device__ __forceinline__ void cp_commit() {
    asm volatile("cp.async.commit_group;" ::: "memory");
}
template<int NN>
__device__ __forceinline__ void cp_wait() {
    asm volatile("cp.async.wait_group %0;" :: "n"(NN) : "memory");
}

__device__ __forceinline__ uint32_t pack2(float a, float b) {
    __nv_bfloat162 t = __floats2bfloat162_rn(a, b);
    return *reinterpret_cast<uint32_t*>(&t);
}

__device__ __forceinline__ void split8(const float4& v0, const float4& v1,
                                       uint4& hi, uint4& lo) {
    float f[8] = {v0.x, v0.y, v0.z, v0.w, v1.x, v1.y, v1.z, v1.w};
    float h[8], l[8];
#pragma unroll
    for (int i = 0; i < 8; ++i) {
        __nv_bfloat16 hb = __float2bfloat16_rn(f[i]);
        float hf = __bfloat162float(hb);
        h[i] = hf;
        l[i] = f[i] - hf;
    }
    hi.x = pack2(h[0], h[1]); hi.y = pack2(h[2], h[3]);
    hi.z = pack2(h[4], h[5]); hi.w = pack2(h[6], h[7]);
    lo.x = pack2(l[0], l[1]); lo.y = pack2(l[2], l[3]);
    lo.z = pack2(l[4], l[5]); lo.w = pack2(l[6], l[7]);
}

// ---------------------------------------------------------------------------
// CSR build (unchanged)
// ---------------------------------------------------------------------------
__global__ void zero_int_kernel(int* __restrict__ a, int* __restrict__ b, int n) {
    int i = blockIdx.x * blockDim.x + threadIdx.x;
    if (i < n) { a[i] = 0; b[i] = 0; }
}

__global__ void degi_kernel(const int* __restrict__ dst, int* __restrict__ deg, int E) {
    int e = blockIdx.x * blockDim.x + threadIdx.x;
    if (e < E) atomicAdd(&deg[dst[e]], 1);
}

__global__ void rdeg_kernel(const int* __restrict__ deg, float* __restrict__ rdeg, int n) {
    int i = blockIdx.x * blockDim.x + threadIdx.x;
    if (i < n) rdeg[i] = 1.0f / fmaxf((float)deg[i], 1.0f);
}

__global__ void scan1_kernel(const int* __restrict__ deg, int* __restrict__ rowptr,
                             int* __restrict__ bsum, int n) {
    __shared__ int warp_tot[8];
    int t = threadIdx.x, lane = t & 31, wid = t >> 5;
    int base = blockIdx.x * 1024 + t * 4;
    int v0 = (base + 0 < n) ? deg[base + 0] : 0;
    int v1 = (base + 1 < n) ? deg[base + 1] : 0;
    int v2 = (base + 2 < n) ? deg[base + 2] : 0;
    int v3 = (base + 3 < n) ? deg[base + 3] : 0;
    int tot = v0 + v1 + v2 + v3;

    int inc = tot;
#pragma unroll
    for (int off = 1; off < 32; off <<= 1) {
        int y = __shfl_up_sync(0xFFFFFFFF, inc, off);
        if (lane >= off) inc += y;
    }
    if (lane == 31) warp_tot[wid] = inc;
    __syncthreads();
    if (wid == 0) {
        int w = (lane < 8) ? warp_tot[lane] : 0;
        int wi = w;
#pragma unroll
        for (int off = 1; off < 8; off <<= 1) {
            int y = __shfl_up_sync(0xFFFFFFFF, wi, off);
            if (lane >= off) wi += y;
        }
        if (lane < 8) warp_tot[lane] = wi - w;
    }
    __syncthreads();
    int excl = warp_tot[wid] + inc - tot;

    if (base + 0 < n) rowptr[base + 0] = excl;
    if (base + 1 < n) rowptr[base + 1] = excl + v0;
    if (base + 2 < n) rowptr[base + 2] = excl + v0 + v1;
    if (base + 3 < n) rowptr[base + 3] = excl + v0 + v1 + v2;
    if (t == 255) bsum[blockIdx.x] = warp_tot[7] + inc;
}

__global__ void scan2_kernel(int* __restrict__ bsum, int nblk) {
    __shared__ int sh[1024];
    int t = threadIdx.x;
#pragma unroll
    for (int i = 0; i < 4; ++i) {
        int idx = t + i * 256;
        sh[idx] = (idx < nblk) ? bsum[idx] : 0;
    }
    __syncthreads();
    for (int off = 1; off < 1024; off <<= 1) {
        int v[4];
#pragma unroll
        for (int i = 0; i < 4; ++i) {
            int idx = t + i * 256;
            v[i] = (idx >= off) ? sh[idx - off] : 0;
        }
        __syncthreads();
#pragma unroll
        for (int i = 0; i < 4; ++i) sh[t + i * 256] += v[i];
        __syncthreads();
    }
#pragma unroll
    for (int i = 0; i < 4; ++i) {
        int idx = t + i * 256;
        if (idx < nblk) bsum[idx] = (idx == 0) ? 0 : sh[idx - 1];
    }
}

__global__ void scan3_kernel(int* __restrict__ rowptr, const int* __restrict__ bsum,
                             int n, int E) {
    int i = blockIdx.x * blockDim.x + threadIdx.x;
    if (i < n) rowptr[i] += bsum[i >> 10];
    if (i == 0) rowptr[n] = E;
}

__global__ void fill_kernel(const int* __restrict__ src, const int* __restrict__ dst,
                            const int* __restrict__ rowptr, int* __restrict__ cursor,
                            int* __restrict__ csr, int E) {
    int e = blockIdx.x * blockDim.x + threadIdx.x;
    if (e >= E) return;
    int d = dst[e];
    int pos = rowptr[d] + atomicAdd(&cursor[d], 1);
    csr[pos] = src[e];
}

// ---------------------------------------------------------------------------
// Gather (fp16 in -> bf16 hi/lo planes out). Warp per node, mean fused.
// 8-edge unroll for MLP.
// ---------------------------------------------------------------------------
__global__ void __launch_bounds__(256)
gather_kernel(const uint2* __restrict__ h2, const int* __restrict__ rowptr,
              const int* __restrict__ csr, const float* __restrict__ rdeg,
              __nv_bfloat16* __restrict__ GH, __nv_bfloat16* __restrict__ GL,
              int n) {
    int gw   = (blockIdx.x * blockDim.x + threadIdx.x) >> 5;
    int lane = threadIdx.x & 31;
    if (gw >= n) return;
    int s0 = rowptr[gw], s1 = rowptr[gw + 1];
    float ax = 0.f, ay = 0.f, az = 0.f, aw = 0.f;
    int j = s0;
    for (; j + 8 <= s1; j += 8) {
        int idx[8];
        uint2 u[8];
#pragma unroll
        for (int q = 0; q < 8; ++q) idx[q] = __ldg(&csr[j + q]);
#pragma unroll
        for (int q = 0; q < 8; ++q) u[q] = h2[(size_t)idx[q] * 32 + lane];
#pragma unroll
        for (int q = 0; q < 8; ++q) {
            float2 p0 = __half22float2(*reinterpret_cast<__half2*>(&u[q].x));
            float2 p1 = __half22float2(*reinterpret_cast<__half2*>(&u[q].y));
            ax += p0.x; ay += p0.y; az += p1.x; aw += p1.y;
        }
    }
    for (; j + 4 <= s1; j += 4) {
        int idx[4];
        uint2 u[4];
#pragma unroll
        for (int q = 0; q < 4; ++q) idx[q] = __ldg(&csr[j + q]);
#pragma unroll
        for (int q = 0; q < 4; ++q) u[q] = h2[(size_t)idx[q] * 32 + lane];
#pragma unroll
        for (int q = 0; q < 4; ++q) {
            float2 p0 = __half22float2(*reinterpret_cast<__half2*>(&u[q].x));
            float2 p1 = __half22float2(*reinterpret_cast<__half2*>(&u[q].y));
            ax += p0.x; ay += p0.y; az += p1.x; aw += p1.y;
        }
    }
    for (; j < s1; ++j) {
        int i0 = __ldg(&csr[j]);
        uint2 u = h2[(size_t)i0 * 32 + lane];
        float2 p0 = __half22float2(*reinterpret_cast<__half2*>(&u.x));
        float2 p1 = __half22float2(*reinterpret_cast<__half2*>(&u.y));
        ax += p0.x; ay += p0.y; az += p1.x; aw += p1.y;
    }
    float rd = rdeg[gw];
    float m[4] = {ax * rd, ay * rd, az * rd, aw * rd};
    float h[4], l[4];
#pragma unroll
    for (int q = 0; q < 4; ++q) {
        __nv_bfloat16 hb = __float2bfloat16_rn(m[q]);
        h[q] = __bfloat162float(hb);
        l[q] = m[q] - h[q];
    }
    uint2 hv = make_uint2(pack2(h[0], h[1]), pack2(h[2], h[3]));
    uint2 lv = make_uint2(pack2(l[0], l[1]), pack2(l[2], l[3]));
    *(uint2*)(GH + (size_t)gw * HID + lane * 4) = hv;
    *(uint2*)(GL + (size_t)gw * HID + lane * 4) = lv;
}

// ---------------------------------------------------------------------------
// Weight prep: transpose + bf16 hi/lo split.
// ---------------------------------------------------------------------------
__global__ void wprep_kernel(const float* __restrict__ W0, const float* __restrict__ W1,
                             int K0, int Ktot, int BNw,
                             __nv_bfloat16* __restrict__ oh,
                             __nv_bfloat16* __restrict__ ol) {
    int i = blockIdx.x * blockDim.x + threadIdx.x;
    if (i >= BNw * Ktot) return;
    int n = i / Ktot, k = i % Ktot;
    float w = (k < K0) ? W0[(size_t)k * BNw + n] : W1[(size_t)(k - K0) * BNw + n];
    __nv_bfloat16 h = __float2bfloat16_rn(w);
    oh[i] = h;
    ol[i] = __float2bfloat16_rn(w - __bfloat162float(h));
}

// ---------------------------------------------------------------------------
// HMMA split-bf16 GEMM (one barrier per chunk in both paths).
// ---------------------------------------------------------------------------
template<int BN, int NC, int NC0, bool RELU, bool AFF, bool WH,
         bool PRESPLIT, bool OUTSPLIT>
__global__ void __launch_bounds__(256, 2)
mma_gemm_kernel(const float* __restrict__ X, int sX,
                const __nv_bfloat16* __restrict__ Ah0,
                const __nv_bfloat16* __restrict__ Al0, int sA0,
                const __nv_bfloat16* __restrict__ Ah1,
                const __nv_bfloat16* __restrict__ Al1, int sA1,
                const __nv_bfloat16* __restrict__ Wh,
                const __nv_bfloat16* __restrict__ Wl,
                const float* __restrict__ bias,
                const float* __restrict__ gamma,
                const float* __restrict__ beta,
                float* __restrict__ C,
                __nv_bfloat16* __restrict__ OH,
                __nv_bfloat16* __restrict__ OL,
                __half* __restrict__ H16, int Nrows)
{
    constexpr int KTOT   = NC * 32;
    constexpr int WN     = BN / 2;
    constexpr int NT8    = WN / 8;
    constexpr int NT16   = WN / 16;
    constexpr int APITCH = 80;
    constexpr int ABYTES = 128 * APITCH;
    constexpr int BBYTES = BN * APITCH;
    constexpr int STAGE  = 2 * ABYTES + 2 * BBYTES;
    constexpr int BPER   = (BN * 4) / 256;

    extern __shared__ __align__(128) char smem[];
    const uint32_t sbase = smem_u32(smem);

    const int tid  = threadIdx.x;
    const int wid  = tid >> 5;
    const int lane = tid & 31;
    const int wm   = wid & 3;
    const int wn   = wid >> 2;
    const int row0 = blockIdx.x * 128;

    float acc[2][NT8][4];
#pragma unroll
    for (int mt = 0; mt < 2; ++mt)
#pragma unroll
        for (int nt = 0; nt < NT8; ++nt)
#pragma unroll
            for (int q = 0; q < 4; ++q) acc[mt][nt][q] = 0.0f;

    float4 af[2][2];

    auto load_tileA_f32 = [&](int c) {
#pragma unroll
        for (int s = 0; s < 2; ++s) {
            int f = tid + s * 256;
            int r = f >> 2, seg = f & 3;
            float4 v0 = make_float4(0.f, 0.f, 0.f, 0.f), v1 = v0;
            int grow = row0 + r;
            if (grow < Nrows) {
                const float* p = X + (size_t)grow * sX + c * 32 + seg * 8;
                v0 = *(const float4*)p;
                v1 = *(const float4*)(p + 4);
            }
            af[s][0] = v0; af[s][1] = v1;
        }
    };

    auto store_tileA_f32 = [&](int buf) {
        char* sp = smem + buf * STAGE;
#pragma unroll
        for (int s = 0; s < 2; ++s) {
            int f = tid + s * 256;
            int r = f >> 2, seg = f & 3;
            uint4 hi, lo;
            split8(af[s][0], af[s][1], hi, lo);
            uint32_t off = (uint32_t)(r * APITCH + seg * 16);
            *(uint4*)(sp + off)          = hi;
            *(uint4*)(sp + ABYTES + off) = lo;
        }
    };

    auto loadA_async = [&](int c, int buf) {
        const __nv_bfloat16 *Hp, *Lp; int stride, koff;
        if (c < NC0) { Hp = Ah0; Lp = Al0; stride = sA0; koff = c * 32; }
        else         { Hp = Ah1; Lp = Al1; stride = sA1; koff = (c - NC0) * 32; }
        const uint32_t abase = sbase + buf * STAGE;
#pragma unroll
        for (int s = 0; s < 2; ++s) {
            int f = tid + s * 256;
            int r = f >> 2, seg = f & 3;
            int grow = row0 + r;
            bool ok = grow < Nrows;
            size_t g = (size_t)(ok ? grow : 0) * stride + koff + seg * 8;
            uint32_t off = (uint32_t)(r * APITCH + seg * 16);
            cp16z(abase + off,          Hp + g, ok);
            cp16z(abase + ABYTES + off, Lp + g, ok);
        }
    };

    auto loadB_async = [&](int c, int buf) {
        const uint32_t bbase = sbase + buf * STAGE + 2 * ABYTES;
#pragma unroll
        for (int s = 0; s < BPER; ++s) {
            int f = tid + s * 256;
            int n = f >> 2, seg = f & 3;
            size_t g = (size_t)n * KTOT + c * 32 + seg * 8;
            uint32_t off = (uint32_t)(n * APITCH + seg * 16);
            cp16(bbase + off,          Wh + g);
            cp16(bbase + BBYTES + off, Wl + g);
        }
    };

    auto compute = [&](int buf) {
        const uint32_t aAh = sbase + buf * STAGE;
        const uint32_t aAl = aAh + ABYTES;
        const uint32_t aBh = aAh + 2 * ABYTES;
        const uint32_t aBl = aBh + BBYTES;
#pragma unroll
        for (int ks = 0; ks < 2; ++ks) {
            uint32_t ah[2][4], al[2][4];
#pragma unroll
            for (int mt = 0; mt < 2; ++mt) {
                uint32_t off = (uint32_t)((wm * 32 + mt * 16 + (lane & 15)) * APITCH
                                          + (ks * 16 + (lane >> 4) * 8) * 2);
                ldsm_x4(ah[mt], aAh + off);
                ldsm_x4(al[mt], aAl + off);
            }
#pragma unroll
            for (int nt2 = 0; nt2 < NT16; ++nt2) {
                uint32_t off = (uint32_t)((wn * WN + nt2 * 16 + (lane & 7)
                                           + ((lane >> 4) & 1) * 8) * APITCH
                                          + (ks * 16 + ((lane >> 3) & 1) * 8) * 2);
                uint32_t bh[4], bl[4];
                ldsm_x4(bh, aBh + off);
                ldsm_x4(bl, aBl + off);
#pragma unroll
                for (int mt = 0; mt < 2; ++mt) {
                    mma_bf16(acc[mt][nt2 * 2 + 0], ah[mt], bh + 0);
                    mma_bf16(acc[mt][nt2 * 2 + 0], ah[mt], bl + 0);
                    mma_bf16(acc[mt][nt2 * 2 + 0], al[mt], bh + 0);
                    mma_bf16(acc[mt][nt2 * 2 + 1], ah[mt], bh + 2);
                    mma_bf16(acc[mt][nt2 * 2 + 1], ah[mt], bl + 2);
                    mma_bf16(acc[mt][nt2 * 2 + 1], al[mt], bh + 2);
                }
            }
        }
    };

    if constexpr (PRESPLIT) {
        // one barrier per chunk: prefetch (c+1) before compute(c), wait after
        loadA_async(0, 0);
        loadB_async(0, 0);
        cp_commit();
        cp_wait<0>();
        __syncthreads();
#pragma unroll
        for (int c = 0; c < NC; ++c) {
            if (c + 1 < NC) {
                loadA_async(c + 1, (c + 1) & 1);
                loadB_async(c + 1, (c + 1) & 1);
                cp_commit();
            }
            compute(c & 1);
            cp_wait<0>();
            __syncthreads();
        }
    } else {
        loadB_async(0, 0);
        cp_commit();
        load_tileA_f32(0);
        store_tileA_f32(0);
        cp_wait<0>();
        __syncthreads();
#pragma unroll
        for (int c = 0; c < NC; ++c) {
            if (c + 1 < NC) {
                loadB_async(c + 1, (c + 1) & 1);
                cp_commit();
                load_tileA_f32(c + 1);
            }
            compute(c & 1);
            if (c + 1 < NC) store_tileA_f32((c + 1) & 1);
            cp_wait<0>();
            __syncthreads();
        }
    }

    // ---- epilogue ----
    const int cb = wn * WN + 2 * (lane & 3);
    float2 scv[NT8], shv[NT8];
#pragma unroll
    for (int nt = 0; nt < NT8; ++nt) {
        int col = cb + nt * 8;
        float s0, h0, s1, h1;
        if constexpr (AFF) {
            s0 = __ldg(&gamma[col])     * rsqrtf(1.0f + 1e-5f);
            s1 = __ldg(&gamma[col + 1]) * rsqrtf(1.0f + 1e-5f);
            h0 = s0 * __ldg(&bias[col])     + __ldg(&beta[col]);
            h1 = s1 * __ldg(&bias[col + 1]) + __ldg(&beta[col + 1]);
        } else {
            s0 = 1.0f; s1 = 1.0f;
            h0 = __ldg(&bias[col]);
            h1 = __ldg(&bias[col + 1]);
        }
        scv[nt] = make_float2(s0, s1);
        shv[nt] = make_float2(h0, h1);
    }
    const int rbase = row0 + wm * 32 + (lane >> 2);
#pragma unroll
    for (int mt = 0; mt < 2; ++mt) {
#pragma unroll
        for (int h = 0; h < 2; ++h) {
            int row = rbase + mt * 16 + h * 8;
            if (row >= Nrows) continue;
#pragma unroll
            for (int nt = 0; nt < NT8; ++nt) {
                float v0 = acc[mt][nt][h * 2 + 0] * scv[nt].x + shv[nt].x;
                float v1 = acc[mt][nt][h * 2 + 1] * scv[nt].y + shv[nt].y;
                if constexpr (RELU) { v0 = fmaxf(v0, 0.0f); v1 = fmaxf(v1, 0.0f); }
                size_t base = (size_t)row * BN + cb + nt * 8;
                if constexpr (OUTSPLIT) {
                    __nv_bfloat16 h0 = __float2bfloat16_rn(v0);
                    __nv_bfloat16 h1 = __float2bfloat16_rn(v1);
                    float l0 = v0 - __bfloat162float(h0);
                    float l1 = v1 - __bfloat162float(h1);
                    *(uint32_t*)(OH + base) = pack2(__bfloat162float(h0), __bfloat162float(h1));
                    *(uint32_t*)(OL + base) = pack2(l0, l1);
                } else {
                    *(float2*)(C + base) = make_float2(v0, v1);
                }
                if constexpr (WH)
                    *(__half2*)(H16 + base) = __floats2half2_rn(v0, v1);
            }
        }
    }
}

// ---------------------------------------------------------------------------
// Host launcher
// ---------------------------------------------------------------------------
extern "C" void kernel_launch(void* const* d_in, const int* in_sizes, int n_in,
                              void* d_out, int out_size)
{
    const float* x     = (const float*)d_in[0];
    const int*   eidx  = (const int*)  d_in[1];
    const float* w_in  = (const float*)d_in[2];
    const float* b_in  = (const float*)d_in[3];
    const float* w_l1  = (const float*)d_in[4];
    const float* b_l1  = (const float*)d_in[5];
    const float* w_r1  = (const float*)d_in[6];
    const float* g1    = (const float*)d_in[7];
    const float* be1   = (const float*)d_in[8];
    const float* w_l2  = (const float*)d_in[9];
    const float* b_l2  = (const float*)d_in[10];
    const float* w_r2  = (const float*)d_in[11];
    const float* g2    = (const float*)d_in[12];
    const float* be2   = (const float*)d_in[13];
    const float* w_out = (const float*)d_in[14];
    const float* b_out = (const float*)d_in[15];
    float* out = (float*)d_out;

    const int N = in_sizes[0] / 256;
    const int E = in_sizes[1] / 2;
    const int* src = eidx;
    const int* dst = eidx + E;

    __nv_bfloat16 *ah, *al, *bh, *bl, *gh, *gl, *wth, *wtl;
    __half* h16;
    float* rdeg;
    int *degi, *cursor, *rowptr, *csr, *bsum;
    cudaGetSymbolAddress((void**)&ah,     g_ah);
    cudaGetSymbolAddress((void**)&al,     g_al);
    cudaGetSymbolAddress((void**)&bh,     g_bh);
    cudaGetSymbolAddress((void**)&bl,     g_bl);
    cudaGetSymbolAddress((void**)&gh,     g_gh);
    cudaGetSymbolAddress((void**)&gl,     g_gl);
    cudaGetSymbolAddress((void**)&h16,    g_h16);
    cudaGetSymbolAddress((void**)&rdeg,   g_rdeg);
    cudaGetSymbolAddress((void**)&degi,   g_degi);
    cudaGetSymbolAddress((void**)&cursor, g_cursor);
    cudaGetSymbolAddress((void**)&rowptr, g_rowptr);
    cudaGetSymbolAddress((void**)&csr,    g_csr);
    cudaGetSymbolAddress((void**)&bsum,   g_bsum);
    cudaGetSymbolAddress((void**)&wth,    g_wth);
    cudaGetSymbolAddress((void**)&wtl,    g_wtl);
    const int WSTR = 128 * 256;

    const int nBlocks    = (N + 255) / 256;
    const int eBlocks    = (E + 255) / 256;
    const int gemmBlocks = (N + 127) / 128;
    const int scanBlocks = (N + 1023) / 1024;
    const int gatherBlocks = (int)(((long long)N * 32 + 255) / 256);

    const int S128 = 2 * (2 * 128 * 80 + 2 * 128 * 80);   // 81920
    const int S64  = 2 * (2 * 128 * 80 + 2 * 64 * 80);    // 61440
    cudaFuncSetAttribute(mma_gemm_kernel<128, 8, 8, true,  false, true,  false, true >,
                         cudaFuncAttributeMaxDynamicSharedMemorySize, S128);
    cudaFuncSetAttribute(mma_gemm_kernel<128, 8, 4, true,  true,  true,  true,  true >,
                         cudaFuncAttributeMaxDynamicSharedMemorySize, S128);
    cudaFuncSetAttribute(mma_gemm_kernel<128, 8, 4, true,  true,  false, true,  true >,
                         cudaFuncAttributeMaxDynamicSharedMemorySize, S128);
    cudaFuncSetAttribute(mma_gemm_kernel<64,  4, 4, false, false, false, true,  false>,
                         cudaFuncAttributeMaxDynamicSharedMemorySize, S64);

    // launch order: input GEMM in ncu's capture slot (4th)
    zero_int_kernel<<<nBlocks, 256>>>(degi, cursor, N);                      // 1
    degi_kernel<<<eBlocks, 256>>>(dst, degi, E);                             // 2
    wprep_kernel<<<(128 * 256 + 255) / 256, 256>>>(w_in, nullptr, 256, 256, 128,
                                                   wth + 0 * WSTR, wtl + 0 * WSTR); // 3
    mma_gemm_kernel<128, 8, 8, true, false, true, false, true>
        <<<gemmBlocks, 256, S128>>>(
        x, 256, nullptr, nullptr, 0, nullptr, nullptr, 0,
        wth + 0 * WSTR, wtl + 0 * WSTR,
        b_in, nullptr, nullptr, nullptr, ah, al, h16, N);                    // 4 <- profiled

    rdeg_kernel<<<nBlocks, 256>>>(degi, rdeg, N);
    scan1_kernel<<<scanBlocks, 256>>>(degi, rowptr, bsum, N);
    scan2_kernel<<<1, 256>>>(bsum, scanBlocks);
    scan3_kernel<<<nBlocks, 256>>>(rowptr, bsum, N, E);
    fill_kernel<<<eBlocks, 256>>>(src, dst, rowptr, cursor, csr, E);

    wprep_kernel<<<(128 * 256 + 255) / 256, 256>>>(w_l1, w_r1, 128, 256, 128,
                                                   wth + 1 * WSTR, wtl + 1 * WSTR);
    wprep_kernel<<<(128 * 256 + 255) / 256, 256>>>(w_l2, w_r2, 128, 256, 128,
                                                   wth + 2 * WSTR, wtl + 2 * WSTR);
    wprep_kernel<<<(64 * 128 + 255) / 256, 256>>>(w_out, nullptr, 128, 128, 64,
                                                  wth + 3 * WSTR, wtl + 3 * WSTR);

    // ---- SAGE layer 1 ----
    gather_kernel<<<gatherBlocks, 256>>>((const uint2*)h16, rowptr, csr, rdeg,
                                         gh, gl, N);
    mma_gemm_kernel<128, 8, 4, true, true, true, true, true>
        <<<gemmBlocks, 256, S128>>>(
        nullptr, 0, gh, gl, 128, ah, al, 128,
        wth + 1 * WSTR, wtl + 1 * WSTR,
        b_l1, g1, be1, nullptr, bh, bl, h16, N);

    // ---- SAGE layer 2 ----
    gather_kernel<<<gatherBlocks, 256>>>((const uint2*)h16, rowptr, csr, rdeg,
                                         gh, gl, N);
    mma_gemm_kernel<128, 8, 4, true, true, false, true, true>
        <<<gemmBlocks, 256, S128>>>(
        nullptr, 0, gh, gl, 128, bh, bl, 128,
        wth + 2 * WSTR, wtl + 2 * WSTR,
        b_l2, g2, be2, nullptr, ah, al, nullptr, N);

    // ---- output layer ----
    mma_gemm_kernel<64, 4, 4, false, false, false, true, false>
        <<<gemmBlocks, 256, S64>>>(
        nullptr, 0, ah, al, 128, nullptr, nullptr, 0,
        wth + 3 * WSTR, wtl + 3 * WSTR,
        b_out, nullptr, nullptr, out, nullptr, nullptr, nullptr, N);
}

// round 12
// speedup vs baseline: 1.6295x; 1.6132x over previous
#include <cuda_runtime.h>
#include <cuda_fp16.h>
#include <cstddef>
#include <cstdint>

// ---------------------------------------------------------------------------
// GNN: relu(x@W_in+b); 2x SAGEConv(mean) + BN(eval) + relu; out GEMM.
// N=100000, E=1.6M, D_IN=256, H=128, D_OUT=64, fp32 in/out.
//
// R11: full fp16 mixed precision (fp16 A x fp16 W, fp32 accumulate).
//   - 1 MMA per k-step (was 3 with split-bf16), operand bytes halved.
//   - activations live in ONE fp16 buffer (GEMM out = gather in = next GEMM A)
//   - weights pre-transposed to fp16 once per launch.
// Accuracy: ~2e-4 expected (threshold 1e-3). CSR + gather pipeline unchanged.
// ---------------------------------------------------------------------------

#define MAX_N 100000
#define MAX_E 1600000
#define HID   128

__device__ __half g_h16a[(size_t)MAX_N * HID];
__device__ __half g_h16b[(size_t)MAX_N * HID];
__device__ __half g_h16c[(size_t)MAX_N * HID];
__device__ __half g_g16 [(size_t)MAX_N * HID];
__device__ float  g_rdeg[MAX_N];
__device__ int    g_degi  [MAX_N];
__device__ int    g_cursor[MAX_N];
__device__ int    g_rowptr[MAX_N + 1];
__device__ int    g_csr   [MAX_E];
__device__ int    g_bsum  [1024];
__device__ __half g_wt[4][128 * 256];   // transposed fp16 weights per GEMM

// ---------------------------------------------------------------------------
// helpers
// ---------------------------------------------------------------------------
__device__ __forceinline__ uint32_t smem_u32(const void* p) {
    uint32_t a;
    asm("{ .reg .u64 t; cvta.to.shared.u64 t, %1; cvt.u32.u64 %0, t; }"
        : "=r"(a) : "l"(p));
    return a;
}

__device__ __forceinline__ void ldsm_x4(uint32_t* r, uint32_t addr) {
    asm volatile("ldmatrix.sync.aligned.m8n8.x4.shared.b16 {%0,%1,%2,%3}, [%4];"
                 : "=r"(r[0]), "=r"(r[1]), "=r"(r[2]), "=r"(r[3]) : "r"(addr));
}

__device__ __forceinline__ void mma_f16(float* c, const uint32_t* a, const uint32_t* b) {
    asm volatile("mma.sync.aligned.m16n8k16.row.col.f32.f16.f16.f32 "
                 "{%0,%1,%2,%3}, {%4,%5,%6,%7}, {%8,%9}, {%0,%1,%2,%3};"
                 : "+f"(c[0]), "+f"(c[1]), "+f"(c[2]), "+f"(c[3])
                 : "r"(a[0]), "r"(a[1]), "r"(a[2]), "r"(a[3]),
                   "r"(b[0]), "r"(b[1]));
}

__device__ __forceinline__ void cp16(uint32_t saddr, const void* gptr) {
    asm volatile("cp.async.ca.shared.global [%0], [%1], 16;"
                 :: "r"(saddr), "l"(gptr) : "memory");
}
__device__ __forceinline__ void cp16z(uint32_t saddr, const void* gptr, bool valid) {
    int sz = valid ? 16 : 0;
    asm volatile("cp.async.ca.shared.global [%0], [%1], 16, %2;"
                 :: "r"(saddr), "l"(gptr), "r"(sz) : "memory");
}
__device__ __forceinline__ void cp_commit() {
    asm volatile("cp.async.commit_group;" ::: "memory");
}
template<int NN>
__device__ __forceinline__ void cp_wait() {
    asm volatile("cp.async.wait_group %0;" :: "n"(NN) : "memory");
}

__device__ __forceinline__ uint32_t packh2(float a, float b) {
    __half2 t = __floats2half2_rn(a, b);
    return *reinterpret_cast<uint32_t*>(&t);
}

// ---------------------------------------------------------------------------
// CSR build (unchanged)
// ---------------------------------------------------------------------------
__global__ void zero_int_kernel(int* __restrict__ a, int* __restrict__ b, int n) {
    int i = blockIdx.x * blockDim.x + threadIdx.x;
    if (i < n) { a[i] = 0; b[i] = 0; }
}

__global__ void degi_kernel(const int* __restrict__ dst, int* __restrict__ deg, int E) {
    int e = blockIdx.x * blockDim.x + threadIdx.x;
    if (e < E) atomicAdd(&deg[dst[e]], 1);
}

__global__ void rdeg_kernel(const int* __restrict__ deg, float* __restrict__ rdeg, int n) {
    int i = blockIdx.x * blockDim.x + threadIdx.x;
    if (i < n) rdeg[i] = 1.0f / fmaxf((float)deg[i], 1.0f);
}

__global__ void scan1_kernel(const int* __restrict__ deg, int* __restrict__ rowptr,
                             int* __restrict__ bsum, int n) {
    __shared__ int warp_tot[8];
    int t = threadIdx.x, lane = t & 31, wid = t >> 5;
    int base = blockIdx.x * 1024 + t * 4;
    int v0 = (base + 0 < n) ? deg[base + 0] : 0;
    int v1 = (base + 1 < n) ? deg[base + 1] : 0;
    int v2 = (base + 2 < n) ? deg[base + 2] : 0;
    int v3 = (base + 3 < n) ? deg[base + 3] : 0;
    int tot = v0 + v1 + v2 + v3;

    int inc = tot;
#pragma unroll
    for (int off = 1; off < 32; off <<= 1) {
        int y = __shfl_up_sync(0xFFFFFFFF, inc, off);
        if (lane >= off) inc += y;
    }
    if (lane == 31) warp_tot[wid] = inc;
    __syncthreads();
    if (wid == 0) {
        int w = (lane < 8) ? warp_tot[lane] : 0;
        int wi = w;
#pragma unroll
        for (int off = 1; off < 8; off <<= 1) {
            int y = __shfl_up_sync(0xFFFFFFFF, wi, off);
            if (lane >= off) wi += y;
        }
        if (lane < 8) warp_tot[lane] = wi - w;
    }
    __syncthreads();
    int excl = warp_tot[wid] + inc - tot;

    if (base + 0 < n) rowptr[base + 0] = excl;
    if (base + 1 < n) rowptr[base + 1] = excl + v0;
    if (base + 2 < n) rowptr[base + 2] = excl + v0 + v1;
    if (base + 3 < n) rowptr[base + 3] = excl + v0 + v1 + v2;
    if (t == 255) bsum[blockIdx.x] = warp_tot[7] + inc;
}

__global__ void scan2_kernel(int* __restrict__ bsum, int nblk) {
    __shared__ int sh[1024];
    int t = threadIdx.x;
#pragma unroll
    for (int i = 0; i < 4; ++i) {
        int idx = t + i * 256;
        sh[idx] = (idx < nblk) ? bsum[idx] : 0;
    }
    __syncthreads();
    for (int off = 1; off < 1024; off <<= 1) {
        int v[4];
#pragma unroll
        for (int i = 0; i < 4; ++i) {
            int idx = t + i * 256;
            v[i] = (idx >= off) ? sh[idx - off] : 0;
        }
        __syncthreads();
#pragma unroll
        for (int i = 0; i < 4; ++i) sh[t + i * 256] += v[i];
        __syncthreads();
    }
#pragma unroll
    for (int i = 0; i < 4; ++i) {
        int idx = t + i * 256;
        if (idx < nblk) bsum[idx] = (idx == 0) ? 0 : sh[idx - 1];
    }
}

__global__ void scan3_kernel(int* __restrict__ rowptr, const int* __restrict__ bsum,
                             int n, int E) {
    int i = blockIdx.x * blockDim.x + threadIdx.x;
    if (i < n) rowptr[i] += bsum[i >> 10];
    if (i == 0) rowptr[n] = E;
}

__global__ void fill_kernel(const int* __restrict__ src, const int* __restrict__ dst,
                            const int* __restrict__ rowptr, int* __restrict__ cursor,
                            int* __restrict__ csr, int E) {
    int e = blockIdx.x * blockDim.x + threadIdx.x;
    if (e >= E) return;
    int d = dst[e];
    int pos = rowptr[d] + atomicAdd(&cursor[d], 1);
    csr[pos] = src[e];
}

// ---------------------------------------------------------------------------
// Gather (fp16 in -> fp16 mean out). Warp per node, 8-edge unroll.
// ---------------------------------------------------------------------------
__global__ void __launch_bounds__(256)
gather_kernel(const uint2* __restrict__ h2, const int* __restrict__ rowptr,
              const int* __restrict__ csr, const float* __restrict__ rdeg,
              __half* __restrict__ G, int n) {
    int gw   = (blockIdx.x * blockDim.x + threadIdx.x) >> 5;
    int lane = threadIdx.x & 31;
    if (gw >= n) return;
    int s0 = rowptr[gw], s1 = rowptr[gw + 1];
    float ax = 0.f, ay = 0.f, az = 0.f, aw = 0.f;
    int j = s0;
    for (; j + 8 <= s1; j += 8) {
        int idx[8];
        uint2 u[8];
#pragma unroll
        for (int q = 0; q < 8; ++q) idx[q] = __ldg(&csr[j + q]);
#pragma unroll
        for (int q = 0; q < 8; ++q) u[q] = h2[(size_t)idx[q] * 32 + lane];
#pragma unroll
        for (int q = 0; q < 8; ++q) {
            float2 p0 = __half22float2(*reinterpret_cast<__half2*>(&u[q].x));
            float2 p1 = __half22float2(*reinterpret_cast<__half2*>(&u[q].y));
            ax += p0.x; ay += p0.y; az += p1.x; aw += p1.y;
        }
    }
    for (; j + 4 <= s1; j += 4) {
        int idx[4];
        uint2 u[4];
#pragma unroll
        for (int q = 0; q < 4; ++q) idx[q] = __ldg(&csr[j + q]);
#pragma unroll
        for (int q = 0; q < 4; ++q) u[q] = h2[(size_t)idx[q] * 32 + lane];
#pragma unroll
        for (int q = 0; q < 4; ++q) {
            float2 p0 = __half22float2(*reinterpret_cast<__half2*>(&u[q].x));
            float2 p1 = __half22float2(*reinterpret_cast<__half2*>(&u[q].y));
            ax += p0.x; ay += p0.y; az += p1.x; aw += p1.y;
        }
    }
    for (; j < s1; ++j) {
        int i0 = __ldg(&csr[j]);
        uint2 u = h2[(size_t)i0 * 32 + lane];
        float2 p0 = __half22float2(*reinterpret_cast<__half2*>(&u.x));
        float2 p1 = __half22float2(*reinterpret_cast<__half2*>(&u.y));
        ax += p0.x; ay += p0.y; az += p1.x; aw += p1.y;
    }
    float rd = rdeg[gw];
    uint2 ov = make_uint2(packh2(ax * rd, ay * rd), packh2(az * rd, aw * rd));
    *(uint2*)(G + (size_t)gw * HID + lane * 4) = ov;
}

// ---------------------------------------------------------------------------
// Weight prep: transpose + fp16.  out[n*Ktot+k] = (half)W[k,n]
// ---------------------------------------------------------------------------
__global__ void wprep_kernel(const float* __restrict__ W0, const float* __restrict__ W1,
                             int K0, int Ktot, int BNw, __half* __restrict__ o) {
    int i = blockIdx.x * blockDim.x + threadIdx.x;
    if (i >= BNw * Ktot) return;
    int n = i / Ktot, k = i % Ktot;
    float w = (k < K0) ? W0[(size_t)k * BNw + n] : W1[(size_t)(k - K0) * BNw + n];
    o[i] = __float2half_rn(w);
}

// ---------------------------------------------------------------------------
// fp16 HMMA GEMM, double-buffered, one barrier per chunk.
//  F32A: A is fp32 (X), converted to fp16 in register staging.
//  else: A from fp16 buffers A0/A1 via cp.async (chunk < NC0 -> A0).
//  OUTF32: write fp32 C; else write fp16 H.
// Block 128 x BN, 8 warps (4x2), warp tile 32 x BN/2, pitch-80 smem.
// ---------------------------------------------------------------------------
template<int BN, int NC, int NC0, bool RELU, bool AFF, bool F32A, bool OUTF32>
__global__ void __launch_bounds__(256, 2)
mma_gemm_kernel(const float* __restrict__ X, int sX,
                const __half* __restrict__ A0, int sA0,
                const __half* __restrict__ A1, int sA1,
                const __half* __restrict__ W,
                const float* __restrict__ bias,
                const float* __restrict__ gamma,
                const float* __restrict__ beta,
                float* __restrict__ C,
                __half* __restrict__ H, int Nrows)
{
    constexpr int KTOT   = NC * 32;
    constexpr int WN     = BN / 2;
    constexpr int NT8    = WN / 8;
    constexpr int NT16   = WN / 16;
    constexpr int APITCH = 80;                // 32 fp16 (64B) + 16B pad
    constexpr int ABYTES = 128 * APITCH;
    constexpr int BBYTES = BN * APITCH;
    constexpr int STAGE  = ABYTES + BBYTES;
    constexpr int BPER   = (BN * 4) / 256;    // B 16B segs per thread

    extern __shared__ __align__(128) char smem[];
    const uint32_t sbase = smem_u32(smem);

    const int tid  = threadIdx.x;
    const int wid  = tid >> 5;
    const int lane = tid & 31;
    const int wm   = wid & 3;
    const int wn   = wid >> 2;
    const int row0 = blockIdx.x * 128;

    float acc[2][NT8][4];
#pragma unroll
    for (int mt = 0; mt < 2; ++mt)
#pragma unroll
        for (int nt = 0; nt < NT8; ++nt)
#pragma unroll
            for (int q = 0; q < 4; ++q) acc[mt][nt][q] = 0.0f;

    float4 af[2][2];   // F32A staging

    auto load_tileA_f32 = [&](int c) {
#pragma unroll
        for (int s = 0; s < 2; ++s) {
            int f = tid + s * 256;
            int r = f >> 2, seg = f & 3;
            float4 v0 = make_float4(0.f, 0.f, 0.f, 0.f), v1 = v0;
            int grow = row0 + r;
            if (grow < Nrows) {
                const float* p = X + (size_t)grow * sX + c * 32 + seg * 8;
                v0 = *(const float4*)p;
                v1 = *(const float4*)(p + 4);
            }
            af[s][0] = v0; af[s][1] = v1;
        }
    };

    auto store_tileA_f16 = [&](int buf) {
        char* sp = smem + buf * STAGE;
#pragma unroll
        for (int s = 0; s < 2; ++s) {
            int f = tid + s * 256;
            int r = f >> 2, seg = f & 3;
            uint4 v;
            v.x = packh2(af[s][0].x, af[s][0].y);
            v.y = packh2(af[s][0].z, af[s][0].w);
            v.z = packh2(af[s][1].x, af[s][1].y);
            v.w = packh2(af[s][1].z, af[s][1].w);
            *(uint4*)(sp + r * APITCH + seg * 16) = v;
        }
    };

    auto loadA_async = [&](int c, int buf) {
        const __half* Ap; int stride, koff;
        if (c < NC0) { Ap = A0; stride = sA0; koff = c * 32; }
        else         { Ap = A1; stride = sA1; koff = (c - NC0) * 32; }
        const uint32_t abase = sbase + buf * STAGE;
#pragma unroll
        for (int s = 0; s < 2; ++s) {
            int f = tid + s * 256;
            int r = f >> 2, seg = f & 3;
            int grow = row0 + r;
            bool ok = grow < Nrows;
            size_t g = (size_t)(ok ? grow : 0) * stride + koff + seg * 8;
            cp16z(abase + r * APITCH + seg * 16, Ap + g, ok);
        }
    };

    auto loadB_async = [&](int c, int buf) {
        const uint32_t bbase = sbase + buf * STAGE + ABYTES;
#pragma unroll
        for (int s = 0; s < BPER; ++s) {
            int f = tid + s * 256;
            int n = f >> 2, seg = f & 3;
            size_t g = (size_t)n * KTOT + c * 32 + seg * 8;
            cp16(bbase + n * APITCH + seg * 16, W + g);
        }
    };

    auto compute = [&](int buf) {
        const uint32_t aA = sbase + buf * STAGE;
        const uint32_t aB = aA + ABYTES;
#pragma unroll
        for (int ks = 0; ks < 2; ++ks) {
            uint32_t a[2][4];
#pragma unroll
            for (int mt = 0; mt < 2; ++mt) {
                uint32_t off = (uint32_t)((wm * 32 + mt * 16 + (lane & 15)) * APITCH
                                          + (ks * 16 + (lane >> 4) * 8) * 2);
                ldsm_x4(a[mt], aA + off);
            }
#pragma unroll
            for (int nt2 = 0; nt2 < NT16; ++nt2) {
                uint32_t off = (uint32_t)((wn * WN + nt2 * 16 + (lane & 7)
                                           + ((lane >> 4) & 1) * 8) * APITCH
                                          + (ks * 16 + ((lane >> 3) & 1) * 8) * 2);
                uint32_t b[4];
                ldsm_x4(b, aB + off);
#pragma unroll
                for (int mt = 0; mt < 2; ++mt) {
                    mma_f16(acc[mt][nt2 * 2 + 0], a[mt], b + 0);
                    mma_f16(acc[mt][nt2 * 2 + 1], a[mt], b + 2);
                }
            }
        }
    };

    if constexpr (!F32A) {
        loadA_async(0, 0);
        loadB_async(0, 0);
        cp_commit();
        cp_wait<0>();
        __syncthreads();
#pragma unroll
        for (int c = 0; c < NC; ++c) {
            if (c + 1 < NC) {
                loadA_async(c + 1, (c + 1) & 1);
                loadB_async(c + 1, (c + 1) & 1);
                cp_commit();
            }
            compute(c & 1);
            cp_wait<0>();
            __syncthreads();
        }
    } else {
        loadB_async(0, 0);
        cp_commit();
        load_tileA_f32(0);
        store_tileA_f16(0);
        cp_wait<0>();
        __syncthreads();
#pragma unroll
        for (int c = 0; c < NC; ++c) {
            if (c + 1 < NC) {
                loadB_async(c + 1, (c + 1) & 1);
                cp_commit();
                load_tileA_f32(c + 1);
            }
            compute(c & 1);
            if (c + 1 < NC) store_tileA_f16((c + 1) & 1);
            cp_wait<0>();
            __syncthreads();
        }
    }

    // ---- epilogue: fused bias/BN/relu ----
    const int cb = wn * WN + 2 * (lane & 3);
    float2 scv[NT8], shv[NT8];
#pragma unroll
    for (int nt = 0; nt < NT8; ++nt) {
        int col = cb + nt * 8;
        float s0, h0, s1, h1;
        if constexpr (AFF) {
            s0 = __ldg(&gamma[col])     * rsqrtf(1.0f + 1e-5f);
            s1 = __ldg(&gamma[col + 1]) * rsqrtf(1.0f + 1e-5f);
            h0 = s0 * __ldg(&bias[col])     + __ldg(&beta[col]);
            h1 = s1 * __ldg(&bias[col + 1]) + __ldg(&beta[col + 1]);
        } else {
            s0 = 1.0f; s1 = 1.0f;
            h0 = __ldg(&bias[col]);
            h1 = __ldg(&bias[col + 1]);
        }
        scv[nt] = make_float2(s0, s1);
        shv[nt] = make_float2(h0, h1);
    }
    const int rbase = row0 + wm * 32 + (lane >> 2);
#pragma unroll
    for (int mt = 0; mt < 2; ++mt) {
#pragma unroll
        for (int h = 0; h < 2; ++h) {
            int row = rbase + mt * 16 + h * 8;
            if (row >= Nrows) continue;
#pragma unroll
            for (int nt = 0; nt < NT8; ++nt) {
                float v0 = acc[mt][nt][h * 2 + 0] * scv[nt].x + shv[nt].x;
                float v1 = acc[mt][nt][h * 2 + 1] * scv[nt].y + shv[nt].y;
                if constexpr (RELU) { v0 = fmaxf(v0, 0.0f); v1 = fmaxf(v1, 0.0f); }
                size_t base = (size_t)row * BN + cb + nt * 8;
                if constexpr (OUTF32) {
                    *(float2*)(C + base) = make_float2(v0, v1);
                } else {
                    *(uint32_t*)(H + base) = packh2(v0, v1);
                }
            }
        }
    }
}

// ---------------------------------------------------------------------------
// Host launcher
// ---------------------------------------------------------------------------
extern "C" void kernel_launch(void* const* d_in, const int* in_sizes, int n_in,
                              void* d_out, int out_size)
{
    const float* x     = (const float*)d_in[0];
    const int*   eidx  = (const int*)  d_in[1];
    const float* w_in  = (const float*)d_in[2];
    const float* b_in  = (const float*)d_in[3];
    const float* w_l1  = (const float*)d_in[4];
    const float* b_l1  = (const float*)d_in[5];
    const float* w_r1  = (const float*)d_in[6];
    const float* g1    = (const float*)d_in[7];
    const float* be1   = (const float*)d_in[8];
    const float* w_l2  = (const float*)d_in[9];
    const float* b_l2  = (const float*)d_in[10];
    const float* w_r2  = (const float*)d_in[11];
    const float* g2    = (const float*)d_in[12];
    const float* be2   = (const float*)d_in[13];
    const float* w_out = (const float*)d_in[14];
    const float* b_out = (const float*)d_in[15];
    float* out = (float*)d_out;

    const int N = in_sizes[0] / 256;
    const int E = in_sizes[1] / 2;
    const int* src = eidx;
    const int* dst = eidx + E;

    __half *h16a, *h16b, *h16c, *g16, *wt;
    float* rdeg;
    int *degi, *cursor, *rowptr, *csr, *bsum;
    cudaGetSymbolAddress((void**)&h16a,   g_h16a);
    cudaGetSymbolAddress((void**)&h16b,   g_h16b);
    cudaGetSymbolAddress((void**)&h16c,   g_h16c);
    cudaGetSymbolAddress((void**)&g16,    g_g16);
    cudaGetSymbolAddress((void**)&rdeg,   g_rdeg);
    cudaGetSymbolAddress((void**)&degi,   g_degi);
    cudaGetSymbolAddress((void**)&cursor, g_cursor);
    cudaGetSymbolAddress((void**)&rowptr, g_rowptr);
    cudaGetSymbolAddress((void**)&csr,    g_csr);
    cudaGetSymbolAddress((void**)&bsum,   g_bsum);
    cudaGetSymbolAddress((void**)&wt,     g_wt);
    const int WSTR = 128 * 256;

    const int nBlocks    = (N + 255) / 256;
    const int eBlocks    = (E + 255) / 256;
    const int gemmBlocks = (N + 127) / 128;
    const int scanBlocks = (N + 1023) / 1024;
    const int gatherBlocks = (int)(((long long)N * 32 + 255) / 256);

    // smem: 2 stages x (A + B), pitch 80
    const int S128 = 2 * (128 * 80 + 128 * 80);   // 40960
    const int S64  = 2 * (128 * 80 + 64 * 80);    // 30720
    cudaFuncSetAttribute(mma_gemm_kernel<128, 8, 8, true,  false, true,  false>,
                         cudaFuncAttributeMaxDynamicSharedMemorySize, S128);
    cudaFuncSetAttribute(mma_gemm_kernel<128, 8, 4, true,  true,  false, false>,
                         cudaFuncAttributeMaxDynamicSharedMemorySize, S128);
    cudaFuncSetAttribute(mma_gemm_kernel<64,  4, 4, false, false, false, true >,
                         cudaFuncAttributeMaxDynamicSharedMemorySize, S64);

    // launch order: input GEMM in ncu's capture slot (4th)
    zero_int_kernel<<<nBlocks, 256>>>(degi, cursor, N);                      // 1
    degi_kernel<<<eBlocks, 256>>>(dst, degi, E);                             // 2
    wprep_kernel<<<(128 * 256 + 255) / 256, 256>>>(w_in, nullptr, 256, 256, 128,
                                                   wt + 0 * WSTR);           // 3
    // input layer: h16a = relu(x @ w_in + b_in)
    mma_gemm_kernel<128, 8, 8, true, false, true, false>
        <<<gemmBlocks, 256, S128>>>(
        x, 256, nullptr, 0, nullptr, 0, wt + 0 * WSTR,
        b_in, nullptr, nullptr, nullptr, h16a, N);                           // 4 <- profiled

    rdeg_kernel<<<nBlocks, 256>>>(degi, rdeg, N);
    scan1_kernel<<<scanBlocks, 256>>>(degi, rowptr, bsum, N);
    scan2_kernel<<<1, 256>>>(bsum, scanBlocks);
    scan3_kernel<<<nBlocks, 256>>>(rowptr, bsum, N, E);
    fill_kernel<<<eBlocks, 256>>>(src, dst, rowptr, cursor, csr, E);

    wprep_kernel<<<(128 * 256 + 255) / 256, 256>>>(w_l1, w_r1, 128, 256, 128,
                                                   wt + 1 * WSTR);
    wprep_kernel<<<(128 * 256 + 255) / 256, 256>>>(w_l2, w_r2, 128, 256, 128,
                                                   wt + 2 * WSTR);
    wprep_kernel<<<(64 * 128 + 255) / 256, 256>>>(w_out, nullptr, 128, 128, 64,
                                                  wt + 3 * WSTR);

    // ---- SAGE layer 1: h16b = relu(bn([mean|h16a] @ W1 + b)) ----
    gather_kernel<<<gatherBlocks, 256>>>((const uint2*)h16a, rowptr, csr, rdeg,
                                         g16, N);
    mma_gemm_kernel<128, 8, 4, true, true, false, false>
        <<<gemmBlocks, 256, S128>>>(
        nullptr, 0, g16, 128, h16a, 128, wt + 1 * WSTR,
        b_l1, g1, be1, nullptr, h16b, N);

    // ---- SAGE layer 2: h16c = relu(bn([mean|h16b] @ W2 + b)) ----
    gather_kernel<<<gatherBlocks, 256>>>((const uint2*)h16b, rowptr, csr, rdeg,
                                         g16, N);
    mma_gemm_kernel<128, 8, 4, true, true, false, false>
        <<<gemmBlocks, 256, S128>>>(
        nullptr, 0, g16, 128, h16b, 128, wt + 2 * WSTR,
        b_l2, g2, be2, nullptr, h16c, N);

    // ---- output layer: out = h16c @ w_out + b_out ----
    mma_gemm_kernel<64, 4, 4, false, false, false, true>
        <<<gemmBlocks, 256, S64>>>(
        nullptr, 0, h16c, 128, nullptr, 0, wt + 3 * WSTR,
        b_out, nullptr, nullptr, out, nullptr, N);
}

// round 13
// speedup vs baseline: 1.6609x; 1.0193x over previous
#include <cuda_runtime.h>
#include <cuda_fp16.h>
#include <cstddef>
#include <cstdint>

// ---------------------------------------------------------------------------
// GNN: relu(x@W_in+b); 2x SAGEConv(mean) + BN(eval) + relu; out GEMM.
// N=100000, E=1.6M, D_IN=256, H=128, D_OUT=64, fp32 in/out.
//
// R12: GEMM cp.async pipeline deepened to 3 stages with wait_group 1
// (R11's wait_group 0 drained the in-flight prefetch every chunk -> bubble).
// 4 wprep launches fused into one. fp16 math pipeline unchanged from R11.
// ---------------------------------------------------------------------------

#define MAX_N 100000
#define MAX_E 1600000
#define HID   128

__device__ __half g_h16a[(size_t)MAX_N * HID];
__device__ __half g_h16b[(size_t)MAX_N * HID];
__device__ __half g_h16c[(size_t)MAX_N * HID];
__device__ __half g_g16 [(size_t)MAX_N * HID];
__device__ float  g_rdeg[MAX_N];
__device__ int    g_degi  [MAX_N];
__device__ int    g_cursor[MAX_N];
__device__ int    g_rowptr[MAX_N + 1];
__device__ int    g_csr   [MAX_E];
__device__ int    g_bsum  [1024];
__device__ __half g_wt[4][128 * 256];   // transposed fp16 weights per GEMM

// ---------------------------------------------------------------------------
// helpers
// ---------------------------------------------------------------------------
__device__ __forceinline__ uint32_t smem_u32(const void* p) {
    uint32_t a;
    asm("{ .reg .u64 t; cvta.to.shared.u64 t, %1; cvt.u32.u64 %0, t; }"
        : "=r"(a) : "l"(p));
    return a;
}

__device__ __forceinline__ void ldsm_x4(uint32_t* r, uint32_t addr) {
    asm volatile("ldmatrix.sync.aligned.m8n8.x4.shared.b16 {%0,%1,%2,%3}, [%4];"
                 : "=r"(r[0]), "=r"(r[1]), "=r"(r[2]), "=r"(r[3]) : "r"(addr));
}

__device__ __forceinline__ void mma_f16(float* c, const uint32_t* a, const uint32_t* b) {
    asm volatile("mma.sync.aligned.m16n8k16.row.col.f32.f16.f16.f32 "
                 "{%0,%1,%2,%3}, {%4,%5,%6,%7}, {%8,%9}, {%0,%1,%2,%3};"
                 : "+f"(c[0]), "+f"(c[1]), "+f"(c[2]), "+f"(c[3])
                 : "r"(a[0]), "r"(a[1]), "r"(a[2]), "r"(a[3]),
                   "r"(b[0]), "r"(b[1]));
}

__device__ __forceinline__ void cp16(uint32_t saddr, const void* gptr) {
    asm volatile("cp.async.ca.shared.global [%0], [%1], 16;"
                 :: "r"(saddr), "l"(gptr) : "memory");
}
__device__ __forceinline__ void cp16z(uint32_t saddr, const void* gptr, bool valid) {
    int sz = valid ? 16 : 0;
    asm volatile("cp.async.ca.shared.global [%0], [%1], 16, %2;"
                 :: "r"(saddr), "l"(gptr), "r"(sz) : "memory");
}
__device__ __forceinline__ void cp_commit() {
    asm volatile("cp.async.commit_group;" ::: "memory");
}
template<int NN>
__device__ __forceinline__ void cp_wait() {
    asm volatile("cp.async.wait_group %0;" :: "n"(NN) : "memory");
}

__device__ __forceinline__ uint32_t packh2(float a, float b) {
    __half2 t = __floats2half2_rn(a, b);
    return *reinterpret_cast<uint32_t*>(&t);
}

// ---------------------------------------------------------------------------
// CSR build (unchanged)
// ---------------------------------------------------------------------------
__global__ void zero_int_kernel(int* __restrict__ a, int* __restrict__ b, int n) {
    int i = blockIdx.x * blockDim.x + threadIdx.x;
    if (i < n) { a[i] = 0; b[i] = 0; }
}

__global__ void degi_kernel(const int* __restrict__ dst, int* __restrict__ deg, int E) {
    int e = blockIdx.x * blockDim.x + threadIdx.x;
    if (e < E) atomicAdd(&deg[dst[e]], 1);
}

__global__ void rdeg_kernel(const int* __restrict__ deg, float* __restrict__ rdeg, int n) {
    int i = blockIdx.x * blockDim.x + threadIdx.x;
    if (i < n) rdeg[i] = 1.0f / fmaxf((float)deg[i], 1.0f);
}

__global__ void scan1_kernel(const int* __restrict__ deg, int* __restrict__ rowptr,
                             int* __restrict__ bsum, int n) {
    __shared__ int warp_tot[8];
    int t = threadIdx.x, lane = t & 31, wid = t >> 5;
    int base = blockIdx.x * 1024 + t * 4;
    int v0 = (base + 0 < n) ? deg[base + 0] : 0;
    int v1 = (base + 1 < n) ? deg[base + 1] : 0;
    int v2 = (base + 2 < n) ? deg[base + 2] : 0;
    int v3 = (base + 3 < n) ? deg[base + 3] : 0;
    int tot = v0 + v1 + v2 + v3;

    int inc = tot;
#pragma unroll
    for (int off = 1; off < 32; off <<= 1) {
        int y = __shfl_up_sync(0xFFFFFFFF, inc, off);
        if (lane >= off) inc += y;
    }
    if (lane == 31) warp_tot[wid] = inc;
    __syncthreads();
    if (wid == 0) {
        int w = (lane < 8) ? warp_tot[lane] : 0;
        int wi = w;
#pragma unroll
        for (int off = 1; off < 8; off <<= 1) {
            int y = __shfl_up_sync(0xFFFFFFFF, wi, off);
            if (lane >= off) wi += y;
        }
        if (lane < 8) warp_tot[lane] = wi - w;
    }
    __syncthreads();
    int excl = warp_tot[wid] + inc - tot;

    if (base + 0 < n) rowptr[base + 0] = excl;
    if (base + 1 < n) rowptr[base + 1] = excl + v0;
    if (base + 2 < n) rowptr[base + 2] = excl + v0 + v1;
    if (base + 3 < n) rowptr[base + 3] = excl + v0 + v1 + v2;
    if (t == 255) bsum[blockIdx.x] = warp_tot[7] + inc;
}

__global__ void scan2_kernel(int* __restrict__ bsum, int nblk) {
    __shared__ int sh[1024];
    int t = threadIdx.x;
#pragma unroll
    for (int i = 0; i < 4; ++i) {
        int idx = t + i * 256;
        sh[idx] = (idx < nblk) ? bsum[idx] : 0;
    }
    __syncthreads();
    for (int off = 1; off < 1024; off <<= 1) {
        int v[4];
#pragma unroll
        for (int i = 0; i < 4; ++i) {
            int idx = t + i * 256;
            v[i] = (idx >= off) ? sh[idx - off] : 0;
        }
        __syncthreads();
#pragma unroll
        for (int i = 0; i < 4; ++i) sh[t + i * 256] += v[i];
        __syncthreads();
    }
#pragma unroll
    for (int i = 0; i < 4; ++i) {
        int idx = t + i * 256;
        if (idx < nblk) bsum[idx] = (idx == 0) ? 0 : sh[idx - 1];
    }
}

__global__ void scan3_kernel(int* __restrict__ rowptr, const int* __restrict__ bsum,
                             int n, int E) {
    int i = blockIdx.x * blockDim.x + threadIdx.x;
    if (i < n) rowptr[i] += bsum[i >> 10];
    if (i == 0) rowptr[n] = E;
}

__global__ void fill_kernel(const int* __restrict__ src, const int* __restrict__ dst,
                            const int* __restrict__ rowptr, int* __restrict__ cursor,
                            int* __restrict__ csr, int E) {
    int e = blockIdx.x * blockDim.x + threadIdx.x;
    if (e >= E) return;
    int d = dst[e];
    int pos = rowptr[d] + atomicAdd(&cursor[d], 1);
    csr[pos] = src[e];
}

// ---------------------------------------------------------------------------
// Gather (fp16 in -> fp16 mean out). Warp per node, 8-edge unroll.
// ---------------------------------------------------------------------------
__global__ void __launch_bounds__(256)
gather_kernel(const uint2* __restrict__ h2, const int* __restrict__ rowptr,
              const int* __restrict__ csr, const float* __restrict__ rdeg,
              __half* __restrict__ G, int n) {
    int gw   = (blockIdx.x * blockDim.x + threadIdx.x) >> 5;
    int lane = threadIdx.x & 31;
    if (gw >= n) return;
    int s0 = rowptr[gw], s1 = rowptr[gw + 1];
    float ax = 0.f, ay = 0.f, az = 0.f, aw = 0.f;
    int j = s0;
    for (; j + 8 <= s1; j += 8) {
        int idx[8];
        uint2 u[8];
#pragma unroll
        for (int q = 0; q < 8; ++q) idx[q] = __ldg(&csr[j + q]);
#pragma unroll
        for (int q = 0; q < 8; ++q) u[q] = h2[(size_t)idx[q] * 32 + lane];
#pragma unroll
        for (int q = 0; q < 8; ++q) {
            float2 p0 = __half22float2(*reinterpret_cast<__half2*>(&u[q].x));
            float2 p1 = __half22float2(*reinterpret_cast<__half2*>(&u[q].y));
            ax += p0.x; ay += p0.y; az += p1.x; aw += p1.y;
        }
    }
    for (; j + 4 <= s1; j += 4) {
        int idx[4];
        uint2 u[4];
#pragma unroll
        for (int q = 0; q < 4; ++q) idx[q] = __ldg(&csr[j + q]);
#pragma unroll
        for (int q = 0; q < 4; ++q) u[q] = h2[(size_t)idx[q] * 32 + lane];
#pragma unroll
        for (int q = 0; q < 4; ++q) {
            float2 p0 = __half22float2(*reinterpret_cast<__half2*>(&u[q].x));
            float2 p1 = __half22float2(*reinterpret_cast<__half2*>(&u[q].y));
            ax += p0.x; ay += p0.y; az += p1.x; aw += p1.y;
        }
    }
    for (; j < s1; ++j) {
        int i0 = __ldg(&csr[j]);
        uint2 u = h2[(size_t)i0 * 32 + lane];
        float2 p0 = __half22float2(*reinterpret_cast<__half2*>(&u.x));
        float2 p1 = __half22float2(*reinterpret_cast<__half2*>(&u.y));
        ax += p0.x; ay += p0.y; az += p1.x; aw += p1.y;
    }
    float rd = rdeg[gw];
    uint2 ov = make_uint2(packh2(ax * rd, ay * rd), packh2(az * rd, aw * rd));
    *(uint2*)(G + (size_t)gw * HID + lane * 4) = ov;
}

// ---------------------------------------------------------------------------
// Fused weight prep: all 4 GEMM weights transposed to fp16 in one launch.
// segments: [0]=w_in(256x128), [1]=w_l1|w_r1, [2]=w_l2|w_r2, [3]=w_out(128x64)
// ---------------------------------------------------------------------------
__global__ void wprep_all_kernel(const float* __restrict__ w_in,
                                 const float* __restrict__ wl1,
                                 const float* __restrict__ wr1,
                                 const float* __restrict__ wl2,
                                 const float* __restrict__ wr2,
                                 const float* __restrict__ wo,
                                 __half* __restrict__ wt) {
    int i = blockIdx.x * blockDim.x + threadIdx.x;
    const float *W0, *W1; int K0, Ktot, BNw, j; __half* o;
    if (i < 32768)        { j = i;         W0 = w_in; W1 = nullptr; K0 = 256; Ktot = 256; BNw = 128; o = wt; }
    else if (i < 65536)   { j = i - 32768; W0 = wl1;  W1 = wr1;     K0 = 128; Ktot = 256; BNw = 128; o = wt + 32768; }
    else if (i < 98304)   { j = i - 65536; W0 = wl2;  W1 = wr2;     K0 = 128; Ktot = 256; BNw = 128; o = wt + 65536; }
    else if (i < 106496)  { j = i - 98304; W0 = wo;   W1 = nullptr; K0 = 128; Ktot = 128; BNw = 64;  o = wt + 98304; }
    else return;
    int n = j / Ktot, k = j % Ktot;
    float w = (k < K0) ? W0[(size_t)k * BNw + n] : W1[(size_t)(k - K0) * BNw + n];
    o[j] = __float2half_rn(w);
}

// ---------------------------------------------------------------------------
// fp16 HMMA GEMM, 3-stage cp.async pipeline (wait_group 1).
//  F32A: A is fp32 (X), converted to fp16 in register staging.
//  else: A from fp16 buffers A0/A1 via cp.async (chunk < NC0 -> A0).
//  OUTF32: write fp32 C; else write fp16 H.
// Block 128 x BN, 8 warps (4x2), warp tile 32 x BN/2, pitch-80 smem.
// ---------------------------------------------------------------------------
template<int BN, int NC, int NC0, bool RELU, bool AFF, bool F32A, bool OUTF32>
__global__ void __launch_bounds__(256, 2)
mma_gemm_kernel(const float* __restrict__ X, int sX,
                const __half* __restrict__ A0, int sA0,
                const __half* __restrict__ A1, int sA1,
                const __half* __restrict__ W,
                const float* __restrict__ bias,
                const float* __restrict__ gamma,
                const float* __restrict__ beta,
                float* __restrict__ C,
                __half* __restrict__ H, int Nrows)
{
    constexpr int KTOT   = NC * 32;
    constexpr int WN     = BN / 2;
    constexpr int NT8    = WN / 8;
    constexpr int NT16   = WN / 16;
    constexpr int APITCH = 80;                // 32 fp16 (64B) + 16B pad
    constexpr int ABYTES = 128 * APITCH;
    constexpr int BBYTES = BN * APITCH;
    constexpr int STAGE  = ABYTES + BBYTES;
    constexpr int BPER   = (BN * 4) / 256;

    extern __shared__ __align__(128) char smem[];
    const uint32_t sbase = smem_u32(smem);

    const int tid  = threadIdx.x;
    const int wid  = tid >> 5;
    const int lane = tid & 31;
    const int wm   = wid & 3;
    const int wn   = wid >> 2;
    const int row0 = blockIdx.x * 128;

    float acc[2][NT8][4];
#pragma unroll
    for (int mt = 0; mt < 2; ++mt)
#pragma unroll
        for (int nt = 0; nt < NT8; ++nt)
#pragma unroll
            for (int q = 0; q < 4; ++q) acc[mt][nt][q] = 0.0f;

    float4 af[2][2];   // F32A staging

    auto load_tileA_f32 = [&](int c) {
#pragma unroll
        for (int s = 0; s < 2; ++s) {
            int f = tid + s * 256;
            int r = f >> 2, seg = f & 3;
            float4 v0 = make_float4(0.f, 0.f, 0.f, 0.f), v1 = v0;
            int grow = row0 + r;
            if (grow < Nrows) {
                const float* p = X + (size_t)grow * sX + c * 32 + seg * 8;
                v0 = *(const float4*)p;
                v1 = *(const float4*)(p + 4);
            }
            af[s][0] = v0; af[s][1] = v1;
        }
    };

    auto store_tileA_f16 = [&](int buf) {
        char* sp = smem + buf * STAGE;
#pragma unroll
        for (int s = 0; s < 2; ++s) {
            int f = tid + s * 256;
            int r = f >> 2, seg = f & 3;
            uint4 v;
            v.x = packh2(af[s][0].x, af[s][0].y);
            v.y = packh2(af[s][0].z, af[s][0].w);
            v.z = packh2(af[s][1].x, af[s][1].y);
            v.w = packh2(af[s][1].z, af[s][1].w);
            *(uint4*)(sp + r * APITCH + seg * 16) = v;
        }
    };

    auto loadA_async = [&](int c, int buf) {
        const __half* Ap; int stride, koff;
        if (c < NC0) { Ap = A0; stride = sA0; koff = c * 32; }
        else         { Ap = A1; stride = sA1; koff = (c - NC0) * 32; }
        const uint32_t abase = sbase + buf * STAGE;
#pragma unroll
        for (int s = 0; s < 2; ++s) {
            int f = tid + s * 256;
            int r = f >> 2, seg = f & 3;
            int grow = row0 + r;
            bool ok = grow < Nrows;
            size_t g = (size_t)(ok ? grow : 0) * stride + koff + seg * 8;
            cp16z(abase + r * APITCH + seg * 16, Ap + g, ok);
        }
    };

    auto loadB_async = [&](int c, int buf) {
        const uint32_t bbase = sbase + buf * STAGE + ABYTES;
#pragma unroll
        for (int s = 0; s < BPER; ++s) {
            int f = tid + s * 256;
            int n = f >> 2, seg = f & 3;
            size_t g = (size_t)n * KTOT + c * 32 + seg * 8;
            cp16(bbase + n * APITCH + seg * 16, W + g);
        }
    };

    auto compute = [&](int buf) {
        const uint32_t aA = sbase + buf * STAGE;
        const uint32_t aB = aA + ABYTES;
#pragma unroll
        for (int ks = 0; ks < 2; ++ks) {
            uint32_t a[2][4];
#pragma unroll
            for (int mt = 0; mt < 2; ++mt) {
                uint32_t off = (uint32_t)((wm * 32 + mt * 16 + (lane & 15)) * APITCH
                                          + (ks * 16 + (lane >> 4) * 8) * 2);
                ldsm_x4(a[mt], aA + off);
            }
#pragma unroll
            for (int nt2 = 0; nt2 < NT16; ++nt2) {
                uint32_t off = (uint32_t)((wn * WN + nt2 * 16 + (lane & 7)
                                           + ((lane >> 4) & 1) * 8) * APITCH
                                          + (ks * 16 + ((lane >> 3) & 1) * 8) * 2);
                uint32_t b[4];
                ldsm_x4(b, aB + off);
#pragma unroll
                for (int mt = 0; mt < 2; ++mt) {
                    mma_f16(acc[mt][nt2 * 2 + 0], a[mt], b + 0);
                    mma_f16(acc[mt][nt2 * 2 + 1], a[mt], b + 2);
                }
            }
        }
    };

    if constexpr (!F32A) {
        // 3-stage: groups c and c+1 in flight; wait_group 1 before compute(c)
        loadA_async(0, 0); loadB_async(0, 0); cp_commit();
        loadA_async(1, 1); loadB_async(1, 1); cp_commit();
#pragma unroll
        for (int c = 0; c < NC; ++c) {
            if (c == NC - 1) cp_wait<0>(); else cp_wait<1>();
            __syncthreads();
            compute(c % 3);
            if (c + 2 < NC) {
                loadA_async(c + 2, (c + 2) % 3);
                loadB_async(c + 2, (c + 2) % 3);
                cp_commit();
            }
        }
    } else {
        loadB_async(0, 0); cp_commit();
        loadB_async(1, 1); cp_commit();
        load_tileA_f32(0); store_tileA_f16(0);
        load_tileA_f32(1); store_tileA_f16(1);
#pragma unroll
        for (int c = 0; c < NC; ++c) {
            if (c == NC - 1) cp_wait<0>(); else cp_wait<1>();
            __syncthreads();
            compute(c % 3);
            if (c + 2 < NC) {
                loadB_async(c + 2, (c + 2) % 3);
                cp_commit();
                load_tileA_f32(c + 2);
                store_tileA_f16((c + 2) % 3);
            }
        }
    }

    // ---- epilogue: fused bias/BN/relu ----
    const int cb = wn * WN + 2 * (lane & 3);
    float2 scv[NT8], shv[NT8];
#pragma unroll
    for (int nt = 0; nt < NT8; ++nt) {
        int col = cb + nt * 8;
        float s0, h0, s1, h1;
        if constexpr (AFF) {
            s0 = __ldg(&gamma[col])     * rsqrtf(1.0f + 1e-5f);
            s1 = __ldg(&gamma[col + 1]) * rsqrtf(1.0f + 1e-5f);
            h0 = s0 * __ldg(&bias[col])     + __ldg(&beta[col]);
            h1 = s1 * __ldg(&bias[col + 1]) + __ldg(&beta[col + 1]);
        } else {
            s0 = 1.0f; s1 = 1.0f;
            h0 = __ldg(&bias[col]);
            h1 = __ldg(&bias[col + 1]);
        }
        scv[nt] = make_float2(s0, s1);
        shv[nt] = make_float2(h0, h1);
    }
    const int rbase = row0 + wm * 32 + (lane >> 2);
#pragma unroll
    for (int mt = 0; mt < 2; ++mt) {
#pragma unroll
        for (int h = 0; h < 2; ++h) {
            int row = rbase + mt * 16 + h * 8;
            if (row >= Nrows) continue;
#pragma unroll
            for (int nt = 0; nt < NT8; ++nt) {
                float v0 = acc[mt][nt][h * 2 + 0] * scv[nt].x + shv[nt].x;
                float v1 = acc[mt][nt][h * 2 + 1] * scv[nt].y + shv[nt].y;
                if constexpr (RELU) { v0 = fmaxf(v0, 0.0f); v1 = fmaxf(v1, 0.0f); }
                size_t base = (size_t)row * BN + cb + nt * 8;
                if constexpr (OUTF32) {
                    *(float2*)(C + base) = make_float2(v0, v1);
                } else {
                    *(uint32_t*)(H + base) = packh2(v0, v1);
                }
            }
        }
    }
}

// ---------------------------------------------------------------------------
// Host launcher
// ---------------------------------------------------------------------------
extern "C" void kernel_launch(void* const* d_in, const int* in_sizes, int n_in,
                              void* d_out, int out_size)
{
    const float* x     = (const float*)d_in[0];
    const int*   eidx  = (const int*)  d_in[1];
    const float* w_in  = (const float*)d_in[2];
    const float* b_in  = (const float*)d_in[3];
    const float* w_l1  = (const float*)d_in[4];
    const float* b_l1  = (const float*)d_in[5];
    const float* w_r1  = (const float*)d_in[6];
    const float* g1    = (const float*)d_in[7];
    const float* be1   = (const float*)d_in[8];
    const float* w_l2  = (const float*)d_in[9];
    const float* b_l2  = (const float*)d_in[10];
    const float* w_r2  = (const float*)d_in[11];
    const float* g2    = (const float*)d_in[12];
    const float* be2   = (const float*)d_in[13];
    const float* w_out = (const float*)d_in[14];
    const float* b_out = (const float*)d_in[15];
    float* out = (float*)d_out;

    const int N = in_sizes[0] / 256;
    const int E = in_sizes[1] / 2;
    const int* src = eidx;
    const int* dst = eidx + E;

    __half *h16a, *h16b, *h16c, *g16, *wt;
    float* rdeg;
    int *degi, *cursor, *rowptr, *csr, *bsum;
    cudaGetSymbolAddress((void**)&h16a,   g_h16a);
    cudaGetSymbolAddress((void**)&h16b,   g_h16b);
    cudaGetSymbolAddress((void**)&h16c,   g_h16c);
    cudaGetSymbolAddress((void**)&g16,    g_g16);
    cudaGetSymbolAddress((void**)&rdeg,   g_rdeg);
    cudaGetSymbolAddress((void**)&degi,   g_degi);
    cudaGetSymbolAddress((void**)&cursor, g_cursor);
    cudaGetSymbolAddress((void**)&rowptr, g_rowptr);
    cudaGetSymbolAddress((void**)&csr,    g_csr);
    cudaGetSymbolAddress((void**)&bsum,   g_bsum);
    cudaGetSymbolAddress((void**)&wt,     g_wt);
    const int WSTR = 128 * 256;

    const int nBlocks    = (N + 255) / 256;
    const int eBlocks    = (E + 255) / 256;
    const int gemmBlocks = (N + 127) / 128;
    const int scanBlocks = (N + 1023) / 1024;
    const int gatherBlocks = (int)(((long long)N * 32 + 255) / 256);

    // smem: 3 stages x (A + B), pitch 80
    const int S128 = 3 * (128 * 80 + 128 * 80);   // 61440
    const int S64  = 3 * (128 * 80 + 64 * 80);    // 46080
    cudaFuncSetAttribute(mma_gemm_kernel<128, 8, 8, true,  false, true,  false>,
                         cudaFuncAttributeMaxDynamicSharedMemorySize, S128);
    cudaFuncSetAttribute(mma_gemm_kernel<128, 8, 4, true,  true,  false, false>,
                         cudaFuncAttributeMaxDynamicSharedMemorySize, S128);
    cudaFuncSetAttribute(mma_gemm_kernel<64,  4, 4, false, false, false, true >,
                         cudaFuncAttributeMaxDynamicSharedMemorySize, S64);

    // launch order: input GEMM in ncu's capture slot (4th)
    zero_int_kernel<<<nBlocks, 256>>>(degi, cursor, N);                      // 1
    degi_kernel<<<eBlocks, 256>>>(dst, degi, E);                             // 2
    wprep_all_kernel<<<(106496 + 255) / 256, 256>>>(w_in, w_l1, w_r1,
                                                    w_l2, w_r2, w_out, wt);  // 3
    // input layer: h16a = relu(x @ w_in + b_in)
    mma_gemm_kernel<128, 8, 8, true, false, true, false>
        <<<gemmBlocks, 256, S128>>>(
        x, 256, nullptr, 0, nullptr, 0, wt + 0 * WSTR,
        b_in, nullptr, nullptr, nullptr, h16a, N);                           // 4 <- profiled

    rdeg_kernel<<<nBlocks, 256>>>(degi, rdeg, N);
    scan1_kernel<<<scanBlocks, 256>>>(degi, rowptr, bsum, N);
    scan2_kernel<<<1, 256>>>(bsum, scanBlocks);
    scan3_kernel<<<nBlocks, 256>>>(rowptr, bsum, N, E);
    fill_kernel<<<eBlocks, 256>>>(src, dst, rowptr, cursor, csr, E);

    // ---- SAGE layer 1: h16b = relu(bn([mean|h16a] @ W1 + b)) ----
    gather_kernel<<<gatherBlocks, 256>>>((const uint2*)h16a, rowptr, csr, rdeg,
                                         g16, N);
    mma_gemm_kernel<128, 8, 4, true, true, false, false>
        <<<gemmBlocks, 256, S128>>>(
        nullptr, 0, g16, 128, h16a, 128, wt + 1 * WSTR,
        b_l1, g1, be1, nullptr, h16b, N);

    // ---- SAGE layer 2: h16c = relu(bn([mean|h16b] @ W2 + b)) ----
    gather_kernel<<<gatherBlocks, 256>>>((const uint2*)h16b, rowptr, csr, rdeg,
                                         g16, N);
    mma_gemm_kernel<128, 8, 4, true, true, false, false>
        <<<gemmBlocks, 256, S128>>>(
        nullptr, 0, g16, 128, h16b, 128, wt + 2 * WSTR,
        b_l2, g2, be2, nullptr, h16c, N);

    // ---- output layer: out = h16c @ w_out + b_out ----
    mma_gemm_kernel<64, 4, 4, false, false, false, true>
        <<<gemmBlocks, 256, S64>>>(
        nullptr, 0, h16c, 128, nullptr, 0, wt + 3 * WSTR,
        b_out, nullptr, nullptr, out, nullptr, N);
}

// round 14
// speedup vs baseline: 1.6732x; 1.0074x over previous
#include <cuda_runtime.h>
#include <cuda_fp16.h>
#include <cstddef>
#include <cstdint>

// ---------------------------------------------------------------------------
// GNN: relu(x@W_in+b); 2x SAGEConv(mean) + BN(eval) + relu; out GEMM.
// N=100000, E=1.6M, D_IN=256, H=128, D_OUT=64, fp32 in/out.
//
// R13: persistent GEMM CTAs (grid=304) with the FULL fp16 weight matrix
// smem-resident (loaded once per CTA); per row-block only the 10KB A tile is
// pipelined (3-stage cp.async for fp16 A, 2-stage regs for fp32 input A).
// Weight L2 traffic 50MB -> 19MB per GEMM; B load latency off the loop.
// Gather / CSR / fp16 numerics unchanged from R12.
// ---------------------------------------------------------------------------

#define MAX_N 100000
#define MAX_E 1600000
#define HID   128

__device__ __half g_h16a[(size_t)MAX_N * HID];
__device__ __half g_h16b[(size_t)MAX_N * HID];
__device__ __half g_h16c[(size_t)MAX_N * HID];
__device__ __half g_g16 [(size_t)MAX_N * HID];
__device__ float  g_rdeg[MAX_N];
__device__ int    g_degi  [MAX_N];
__device__ int    g_cursor[MAX_N];
__device__ int    g_rowptr[MAX_N + 1];
__device__ int    g_csr   [MAX_E];
__device__ int    g_bsum  [1024];
__device__ __half g_wt[4][128 * 256];   // transposed fp16 weights per GEMM

// ---------------------------------------------------------------------------
// helpers
// ---------------------------------------------------------------------------
__device__ __forceinline__ uint32_t smem_u32(const void* p) {
    uint32_t a;
    asm("{ .reg .u64 t; cvta.to.shared.u64 t, %1; cvt.u32.u64 %0, t; }"
        : "=r"(a) : "l"(p));
    return a;
}

__device__ __forceinline__ void ldsm_x4(uint32_t* r, uint32_t addr) {
    asm volatile("ldmatrix.sync.aligned.m8n8.x4.shared.b16 {%0,%1,%2,%3}, [%4];"
                 : "=r"(r[0]), "=r"(r[1]), "=r"(r[2]), "=r"(r[3]) : "r"(addr));
}

__device__ __forceinline__ void mma_f16(float* c, const uint32_t* a, const uint32_t* b) {
    asm volatile("mma.sync.aligned.m16n8k16.row.col.f32.f16.f16.f32 "
                 "{%0,%1,%2,%3}, {%4,%5,%6,%7}, {%8,%9}, {%0,%1,%2,%3};"
                 : "+f"(c[0]), "+f"(c[1]), "+f"(c[2]), "+f"(c[3])
                 : "r"(a[0]), "r"(a[1]), "r"(a[2]), "r"(a[3]),
                   "r"(b[0]), "r"(b[1]));
}

__device__ __forceinline__ void cp16(uint32_t saddr, const void* gptr) {
    asm volatile("cp.async.ca.shared.global [%0], [%1], 16;"
                 :: "r"(saddr), "l"(gptr) : "memory");
}
__device__ __forceinline__ void cp16z(uint32_t saddr, const void* gptr, bool valid) {
    int sz = valid ? 16 : 0;
    asm volatile("cp.async.ca.shared.global [%0], [%1], 16, %2;"
                 :: "r"(saddr), "l"(gptr), "r"(sz) : "memory");
}
__device__ __forceinline__ void cp_commit() {
    asm volatile("cp.async.commit_group;" ::: "memory");
}
template<int NN>
__device__ __forceinline__ void cp_wait() {
    asm volatile("cp.async.wait_group %0;" :: "n"(NN) : "memory");
}

__device__ __forceinline__ uint32_t packh2(float a, float b) {
    __half2 t = __floats2half2_rn(a, b);
    return *reinterpret_cast<uint32_t*>(&t);
}

// ---------------------------------------------------------------------------
// CSR build (unchanged)
// ---------------------------------------------------------------------------
__global__ void zero_int_kernel(int* __restrict__ a, int* __restrict__ b, int n) {
    int i = blockIdx.x * blockDim.x + threadIdx.x;
    if (i < n) { a[i] = 0; b[i] = 0; }
}

__global__ void degi_kernel(const int* __restrict__ dst, int* __restrict__ deg, int E) {
    int e = blockIdx.x * blockDim.x + threadIdx.x;
    if (e < E) atomicAdd(&deg[dst[e]], 1);
}

__global__ void rdeg_kernel(const int* __restrict__ deg, float* __restrict__ rdeg, int n) {
    int i = blockIdx.x * blockDim.x + threadIdx.x;
    if (i < n) rdeg[i] = 1.0f / fmaxf((float)deg[i], 1.0f);
}

__global__ void scan1_kernel(const int* __restrict__ deg, int* __restrict__ rowptr,
                             int* __restrict__ bsum, int n) {
    __shared__ int warp_tot[8];
    int t = threadIdx.x, lane = t & 31, wid = t >> 5;
    int base = blockIdx.x * 1024 + t * 4;
    int v0 = (base + 0 < n) ? deg[base + 0] : 0;
    int v1 = (base + 1 < n) ? deg[base + 1] : 0;
    int v2 = (base + 2 < n) ? deg[base + 2] : 0;
    int v3 = (base + 3 < n) ? deg[base + 3] : 0;
    int tot = v0 + v1 + v2 + v3;

    int inc = tot;
#pragma unroll
    for (int off = 1; off < 32; off <<= 1) {
        int y = __shfl_up_sync(0xFFFFFFFF, inc, off);
        if (lane >= off) inc += y;
    }
    if (lane == 31) warp_tot[wid] = inc;
    __syncthreads();
    if (wid == 0) {
        int w = (lane < 8) ? warp_tot[lane] : 0;
        int wi = w;
#pragma unroll
        for (int off = 1; off < 8; off <<= 1) {
            int y = __shfl_up_sync(0xFFFFFFFF, wi, off);
            if (lane >= off) wi += y;
        }
        if (lane < 8) warp_tot[lane] = wi - w;
    }
    __syncthreads();
    int excl = warp_tot[wid] + inc - tot;

    if (base + 0 < n) rowptr[base + 0] = excl;
    if (base + 1 < n) rowptr[base + 1] = excl + v0;
    if (base + 2 < n) rowptr[base + 2] = excl + v0 + v1;
    if (base + 3 < n) rowptr[base + 3] = excl + v0 + v1 + v2;
    if (t == 255) bsum[blockIdx.x] = warp_tot[7] + inc;
}

__global__ void scan2_kernel(int* __restrict__ bsum, int nblk) {
    __shared__ int sh[1024];
    int t = threadIdx.x;
#pragma unroll
    for (int i = 0; i < 4; ++i) {
        int idx = t + i * 256;
        sh[idx] = (idx < nblk) ? bsum[idx] : 0;
    }
    __syncthreads();
    for (int off = 1; off < 1024; off <<= 1) {
        int v[4];
#pragma unroll
        for (int i = 0; i < 4; ++i) {
            int idx = t + i * 256;
            v[i] = (idx >= off) ? sh[idx - off] : 0;
        }
        __syncthreads();
#pragma unroll
        for (int i = 0; i < 4; ++i) sh[t + i * 256] += v[i];
        __syncthreads();
    }
#pragma unroll
    for (int i = 0; i < 4; ++i) {
        int idx = t + i * 256;
        if (idx < nblk) bsum[idx] = (idx == 0) ? 0 : sh[idx - 1];
    }
}

__global__ void scan3_kernel(int* __restrict__ rowptr, const int* __restrict__ bsum,
                             int n, int E) {
    int i = blockIdx.x * blockDim.x + threadIdx.x;
    if (i < n) rowptr[i] += bsum[i >> 10];
    if (i == 0) rowptr[n] = E;
}

__global__ void fill_kernel(const int* __restrict__ src, const int* __restrict__ dst,
                            const int* __restrict__ rowptr, int* __restrict__ cursor,
                            int* __restrict__ csr, int E) {
    int e = blockIdx.x * blockDim.x + threadIdx.x;
    if (e >= E) return;
    int d = dst[e];
    int pos = rowptr[d] + atomicAdd(&cursor[d], 1);
    csr[pos] = src[e];
}

// ---------------------------------------------------------------------------
// Gather (fp16 in -> fp16 mean out). Warp per node, 8-edge unroll.
// ---------------------------------------------------------------------------
__global__ void __launch_bounds__(256)
gather_kernel(const uint2* __restrict__ h2, const int* __restrict__ rowptr,
              const int* __restrict__ csr, const float* __restrict__ rdeg,
              __half* __restrict__ G, int n) {
    int gw   = (blockIdx.x * blockDim.x + threadIdx.x) >> 5;
    int lane = threadIdx.x & 31;
    if (gw >= n) return;
    int s0 = rowptr[gw], s1 = rowptr[gw + 1];
    float ax = 0.f, ay = 0.f, az = 0.f, aw = 0.f;
    int j = s0;
    for (; j + 8 <= s1; j += 8) {
        int idx[8];
        uint2 u[8];
#pragma unroll
        for (int q = 0; q < 8; ++q) idx[q] = __ldg(&csr[j + q]);
#pragma unroll
        for (int q = 0; q < 8; ++q) u[q] = h2[(size_t)idx[q] * 32 + lane];
#pragma unroll
        for (int q = 0; q < 8; ++q) {
            float2 p0 = __half22float2(*reinterpret_cast<__half2*>(&u[q].x));
            float2 p1 = __half22float2(*reinterpret_cast<__half2*>(&u[q].y));
            ax += p0.x; ay += p0.y; az += p1.x; aw += p1.y;
        }
    }
    for (; j + 4 <= s1; j += 4) {
        int idx[4];
        uint2 u[4];
#pragma unroll
        for (int q = 0; q < 4; ++q) idx[q] = __ldg(&csr[j + q]);
#pragma unroll
        for (int q = 0; q < 4; ++q) u[q] = h2[(size_t)idx[q] * 32 + lane];
#pragma unroll
        for (int q = 0; q < 4; ++q) {
            float2 p0 = __half22float2(*reinterpret_cast<__half2*>(&u[q].x));
            float2 p1 = __half22float2(*reinterpret_cast<__half2*>(&u[q].y));
            ax += p0.x; ay += p0.y; az += p1.x; aw += p1.y;
        }
    }
    for (; j < s1; ++j) {
        int i0 = __ldg(&csr[j]);
        uint2 u = h2[(size_t)i0 * 32 + lane];
        float2 p0 = __half22float2(*reinterpret_cast<__half2*>(&u.x));
        float2 p1 = __half22float2(*reinterpret_cast<__half2*>(&u.y));
        ax += p0.x; ay += p0.y; az += p1.x; aw += p1.y;
    }
    float rd = rdeg[gw];
    uint2 ov = make_uint2(packh2(ax * rd, ay * rd), packh2(az * rd, aw * rd));
    *(uint2*)(G + (size_t)gw * HID + lane * 4) = ov;
}

// ---------------------------------------------------------------------------
// Fused weight prep: all 4 GEMM weights transposed to fp16 in one launch.
// ---------------------------------------------------------------------------
__global__ void wprep_all_kernel(const float* __restrict__ w_in,
                                 const float* __restrict__ wl1,
                                 const float* __restrict__ wr1,
                                 const float* __restrict__ wl2,
                                 const float* __restrict__ wr2,
                                 const float* __restrict__ wo,
                                 __half* __restrict__ wt) {
    int i = blockIdx.x * blockDim.x + threadIdx.x;
    const float *W0, *W1; int K0, Ktot, BNw, j; __half* o;
    if (i < 32768)        { j = i;         W0 = w_in; W1 = nullptr; K0 = 256; Ktot = 256; BNw = 128; o = wt; }
    else if (i < 65536)   { j = i - 32768; W0 = wl1;  W1 = wr1;     K0 = 128; Ktot = 256; BNw = 128; o = wt + 32768; }
    else if (i < 98304)   { j = i - 65536; W0 = wl2;  W1 = wr2;     K0 = 128; Ktot = 256; BNw = 128; o = wt + 65536; }
    else if (i < 106496)  { j = i - 98304; W0 = wo;   W1 = nullptr; K0 = 128; Ktot = 128; BNw = 64;  o = wt + 98304; }
    else return;
    int n = j / Ktot, k = j % Ktot;
    float w = (k < K0) ? W0[(size_t)k * BNw + n] : W1[(size_t)(k - K0) * BNw + n];
    o[j] = __float2half_rn(w);
}

// ---------------------------------------------------------------------------
// Persistent fp16 HMMA GEMM. Full B resident in smem (loaded once per CTA);
// CTA loops over row-blocks. A: 3-stage cp.async (fp16) / 2-stage regs (fp32).
// Block 128 x BN, 8 warps (4x2), warp tile 32 x BN/2.
// smem layout: [3 x A-stage (pitch 80)] [B: BN rows x pitch KTOT*2+16]
// ---------------------------------------------------------------------------
template<int BN, int NC, int NC0, bool RELU, bool AFF, bool F32A, bool OUTF32>
__global__ void __launch_bounds__(256, 2)
mma_gemm_kernel(const float* __restrict__ X, int sX,
                const __half* __restrict__ A0, int sA0,
                const __half* __restrict__ A1, int sA1,
                const __half* __restrict__ W,
                const float* __restrict__ bias,
                const float* __restrict__ gamma,
                const float* __restrict__ beta,
                float* __restrict__ C,
                __half* __restrict__ H, int Nrows, int nBlocksRow)
{
    constexpr int KTOT   = NC * 32;
    constexpr int WN     = BN / 2;
    constexpr int NT8    = WN / 8;
    constexpr int NT16   = WN / 16;
    constexpr int APITCH = 80;
    constexpr int ABYTES = 128 * APITCH;
    constexpr int BPITCH = KTOT * 2 + 16;
    constexpr int BOFF   = 3 * ABYTES;
    constexpr int K8     = KTOT / 8;

    extern __shared__ __align__(128) char smem[];
    const uint32_t sbase = smem_u32(smem);
    const uint32_t bbase = sbase + BOFF;

    const int tid  = threadIdx.x;
    const int wid  = tid >> 5;
    const int lane = tid & 31;
    const int wm   = wid & 3;
    const int wn   = wid >> 2;

    // ---- load full B once ----
    for (int s = tid; s < BN * K8; s += 256) {
        int n = s / K8, k8 = s % K8;
        cp16(bbase + n * BPITCH + k8 * 16, W + (size_t)n * KTOT + k8 * 8);
    }
    cp_commit();

    // ---- hoisted epilogue constants (col-dependent only) ----
    const int cb = wn * WN + 2 * (lane & 3);
    float2 scv[NT8], shv[NT8];
#pragma unroll
    for (int nt = 0; nt < NT8; ++nt) {
        int col = cb + nt * 8;
        float s0, h0, s1, h1;
        if constexpr (AFF) {
            s0 = __ldg(&gamma[col])     * rsqrtf(1.0f + 1e-5f);
            s1 = __ldg(&gamma[col + 1]) * rsqrtf(1.0f + 1e-5f);
            h0 = s0 * __ldg(&bias[col])     + __ldg(&beta[col]);
            h1 = s1 * __ldg(&bias[col + 1]) + __ldg(&beta[col + 1]);
        } else {
            s0 = 1.0f; s1 = 1.0f;
            h0 = __ldg(&bias[col]);
            h1 = __ldg(&bias[col + 1]);
        }
        scv[nt] = make_float2(s0, s1);
        shv[nt] = make_float2(h0, h1);
    }

    float4 af[2][2];   // F32A staging

    auto load_tileA_f32 = [&](int row0, int c) {
#pragma unroll
        for (int s = 0; s < 2; ++s) {
            int f = tid + s * 256;
            int r = f >> 2, seg = f & 3;
            float4 v0 = make_float4(0.f, 0.f, 0.f, 0.f), v1 = v0;
            int grow = row0 + r;
            if (grow < Nrows) {
                const float* p = X + (size_t)grow * sX + c * 32 + seg * 8;
                v0 = *(const float4*)p;
                v1 = *(const float4*)(p + 4);
            }
            af[s][0] = v0; af[s][1] = v1;
        }
    };

    auto store_tileA_f16 = [&](int buf) {
        char* sp = smem + buf * ABYTES;
#pragma unroll
        for (int s = 0; s < 2; ++s) {
            int f = tid + s * 256;
            int r = f >> 2, seg = f & 3;
            uint4 v;
            v.x = packh2(af[s][0].x, af[s][0].y);
            v.y = packh2(af[s][0].z, af[s][0].w);
            v.z = packh2(af[s][1].x, af[s][1].y);
            v.w = packh2(af[s][1].z, af[s][1].w);
            *(uint4*)(sp + r * APITCH + seg * 16) = v;
        }
    };

    auto loadA_async = [&](int row0, int c, int buf) {
        const __half* Ap; int stride, koff;
        if (c < NC0) { Ap = A0; stride = sA0; koff = c * 32; }
        else         { Ap = A1; stride = sA1; koff = (c - NC0) * 32; }
        const uint32_t abase = sbase + buf * ABYTES;
#pragma unroll
        for (int s = 0; s < 2; ++s) {
            int f = tid + s * 256;
            int r = f >> 2, seg = f & 3;
            int grow = row0 + r;
            bool ok = grow < Nrows;
            size_t g = (size_t)(ok ? grow : 0) * stride + koff + seg * 8;
            cp16z(abase + r * APITCH + seg * 16, Ap + g, ok);
        }
    };

    float acc[2][NT8][4];

    auto compute = [&](int buf, int c) {
        const uint32_t aA = sbase + buf * ABYTES;
#pragma unroll
        for (int ks = 0; ks < 2; ++ks) {
            uint32_t a[2][4];
#pragma unroll
            for (int mt = 0; mt < 2; ++mt) {
                uint32_t off = (uint32_t)((wm * 32 + mt * 16 + (lane & 15)) * APITCH
                                          + (ks * 16 + (lane >> 4) * 8) * 2);
                ldsm_x4(a[mt], aA + off);
            }
#pragma unroll
            for (int nt2 = 0; nt2 < NT16; ++nt2) {
                int n_idx = wn * WN + nt2 * 16 + (lane & 7) + ((lane >> 4) & 1) * 8;
                int kg    = c * 32 + ks * 16 + ((lane >> 3) & 1) * 8;
                uint32_t b[4];
                ldsm_x4(b, bbase + (uint32_t)(n_idx * BPITCH + kg * 2));
#pragma unroll
                for (int mt = 0; mt < 2; ++mt) {
                    mma_f16(acc[mt][nt2 * 2 + 0], a[mt], b + 0);
                    mma_f16(acc[mt][nt2 * 2 + 1], a[mt], b + 2);
                }
            }
        }
    };

    // ---- persistent loop over row blocks ----
    for (int rb = blockIdx.x; rb < nBlocksRow; rb += gridDim.x) {
        const int row0 = rb * 128;

#pragma unroll
        for (int mt = 0; mt < 2; ++mt)
#pragma unroll
            for (int nt = 0; nt < NT8; ++nt)
#pragma unroll
                for (int q = 0; q < 4; ++q) acc[mt][nt][q] = 0.0f;

        if constexpr (!F32A) {
            loadA_async(row0, 0, 0); cp_commit();
            loadA_async(row0, 1, 1); cp_commit();
#pragma unroll
            for (int c = 0; c < NC; ++c) {
                if (c == NC - 1) cp_wait<0>(); else cp_wait<1>();
                __syncthreads();
                compute(c % 3, c);
                if (c + 2 < NC) {
                    loadA_async(row0, c + 2, (c + 2) % 3);
                    cp_commit();
                }
            }
        } else {
            cp_wait<0>();                 // B (first rb) — no-op afterwards
            load_tileA_f32(row0, 0);
            store_tileA_f16(0);
            __syncthreads();
#pragma unroll
            for (int c = 0; c < NC; ++c) {
                if (c + 1 < NC) load_tileA_f32(row0, c + 1);
                compute(c & 1, c);
                if (c + 1 < NC) store_tileA_f16((c + 1) & 1);
                __syncthreads();
            }
        }

        // ---- epilogue ----
        const int rbase = row0 + wm * 32 + (lane >> 2);
#pragma unroll
        for (int mt = 0; mt < 2; ++mt) {
#pragma unroll
            for (int h = 0; h < 2; ++h) {
                int row = rbase + mt * 16 + h * 8;
                if (row >= Nrows) continue;
#pragma unroll
                for (int nt = 0; nt < NT8; ++nt) {
                    float v0 = acc[mt][nt][h * 2 + 0] * scv[nt].x + shv[nt].x;
                    float v1 = acc[mt][nt][h * 2 + 1] * scv[nt].y + shv[nt].y;
                    if constexpr (RELU) { v0 = fmaxf(v0, 0.0f); v1 = fmaxf(v1, 0.0f); }
                    size_t base = (size_t)row * BN + cb + nt * 8;
                    if constexpr (OUTF32) {
                        *(float2*)(C + base) = make_float2(v0, v1);
                    } else {
                        *(uint32_t*)(H + base) = packh2(v0, v1);
                    }
                }
            }
        }
        __syncthreads();
    }
}

// ---------------------------------------------------------------------------
// Host launcher
// ---------------------------------------------------------------------------
extern "C" void kernel_launch(void* const* d_in, const int* in_sizes, int n_in,
                              void* d_out, int out_size)
{
    const float* x     = (const float*)d_in[0];
    const int*   eidx  = (const int*)  d_in[1];
    const float* w_in  = (const float*)d_in[2];
    const float* b_in  = (const float*)d_in[3];
    const float* w_l1  = (const float*)d_in[4];
    const float* b_l1  = (const float*)d_in[5];
    const float* w_r1  = (const float*)d_in[6];
    const float* g1    = (const float*)d_in[7];
    const float* be1   = (const float*)d_in[8];
    const float* w_l2  = (const float*)d_in[9];
    const float* b_l2  = (const float*)d_in[10];
    const float* w_r2  = (const float*)d_in[11];
    const float* g2    = (const float*)d_in[12];
    const float* be2   = (const float*)d_in[13];
    const float* w_out = (const float*)d_in[14];
    const float* b_out = (const float*)d_in[15];
    float* out = (float*)d_out;

    const int N = in_sizes[0] / 256;
    const int E = in_sizes[1] / 2;
    const int* src = eidx;
    const int* dst = eidx + E;

    __half *h16a, *h16b, *h16c, *g16, *wt;
    float* rdeg;
    int *degi, *cursor, *rowptr, *csr, *bsum;
    cudaGetSymbolAddress((void**)&h16a,   g_h16a);
    cudaGetSymbolAddress((void**)&h16b,   g_h16b);
    cudaGetSymbolAddress((void**)&h16c,   g_h16c);
    cudaGetSymbolAddress((void**)&g16,    g_g16);
    cudaGetSymbolAddress((void**)&rdeg,   g_rdeg);
    cudaGetSymbolAddress((void**)&degi,   g_degi);
    cudaGetSymbolAddress((void**)&cursor, g_cursor);
    cudaGetSymbolAddress((void**)&rowptr, g_rowptr);
    cudaGetSymbolAddress((void**)&csr,    g_csr);
    cudaGetSymbolAddress((void**)&bsum,   g_bsum);
    cudaGetSymbolAddress((void**)&wt,     g_wt);
    const int WSTR = 128 * 256;

    const int nBlocks    = (N + 255) / 256;
    const int eBlocks    = (E + 255) / 256;
    const int rowBlocks  = (N + 127) / 128;
    const int gemmGrid   = 304;              // 2 per SM, persistent
    const int scanBlocks = (N + 1023) / 1024;
    const int gatherBlocks = (int)(((long long)N * 32 + 255) / 256);

    // smem: 3 A stages (pitch 80) + resident B (pitch KTOT*2+16)
    const int S256 = 3 * (128 * 80) + 128 * (256 * 2 + 16);   // 98304
    const int S64  = 3 * (128 * 80) + 64  * (128 * 2 + 16);   // 48128
    cudaFuncSetAttribute(mma_gemm_kernel<128, 8, 8, true,  false, true,  false>,
                         cudaFuncAttributeMaxDynamicSharedMemorySize, S256);
    cudaFuncSetAttribute(mma_gemm_kernel<128, 8, 4, true,  true,  false, false>,
                         cudaFuncAttributeMaxDynamicSharedMemorySize, S256);
    cudaFuncSetAttribute(mma_gemm_kernel<64,  4, 4, false, false, false, true >,
                         cudaFuncAttributeMaxDynamicSharedMemorySize, S64);

    // launch order: input GEMM in ncu's capture slot (4th)
    zero_int_kernel<<<nBlocks, 256>>>(degi, cursor, N);                      // 1
    degi_kernel<<<eBlocks, 256>>>(dst, degi, E);                             // 2
    wprep_all_kernel<<<(106496 + 255) / 256, 256>>>(w_in, w_l1, w_r1,
                                                    w_l2, w_r2, w_out, wt);  // 3
    // input layer: h16a = relu(x @ w_in + b_in)
    mma_gemm_kernel<128, 8, 8, true, false, true, false>
        <<<gemmGrid, 256, S256>>>(
        x, 256, nullptr, 0, nullptr, 0, wt + 0 * WSTR,
        b_in, nullptr, nullptr, nullptr, h16a, N, rowBlocks);                // 4 <- profiled

    rdeg_kernel<<<nBlocks, 256>>>(degi, rdeg, N);
    scan1_kernel<<<scanBlocks, 256>>>(degi, rowptr, bsum, N);
    scan2_kernel<<<1, 256>>>(bsum, scanBlocks);
    scan3_kernel<<<nBlocks, 256>>>(rowptr, bsum, N, E);
    fill_kernel<<<eBlocks, 256>>>(src, dst, rowptr, cursor, csr, E);

    // ---- SAGE layer 1: h16b = relu(bn([mean|h16a] @ W1 + b)) ----
    gather_kernel<<<gatherBlocks, 256>>>((const uint2*)h16a, rowptr, csr, rdeg,
                                         g16, N);
    mma_gemm_kernel<128, 8, 4, true, true, false, false>
        <<<gemmGrid, 256, S256>>>(
        nullptr, 0, g16, 128, h16a, 128, wt + 1 * WSTR,
        b_l1, g1, be1, nullptr, h16b, N, rowBlocks);

    // ---- SAGE layer 2: h16c = relu(bn([mean|h16b] @ W2 + b)) ----
    gather_kernel<<<gatherBlocks, 256>>>((const uint2*)h16b, rowptr, csr, rdeg,
                                         g16, N);
    mma_gemm_kernel<128, 8, 4, true, true, false, false>
        <<<gemmGrid, 256, S256>>>(
        nullptr, 0, g16, 128, h16b, 128, wt + 2 * WSTR,
        b_l2, g2, be2, nullptr, h16c, N, rowBlocks);

    // ---- output layer: out = h16c @ w_out + b_out ----
    mma_gemm_kernel<64, 4, 4, false, false, false, true>
        <<<gemmGrid, 256, S64>>>(
        nullptr, 0, h16c, 128, nullptr, 0, wt + 3 * WSTR,
        b_out, nullptr, nullptr, out, nullptr, N, rowBlocks);
}

// round 15
// speedup vs baseline: 1.7546x; 1.0487x over previous
#include <cuda_runtime.h>
#include <cuda_fp16.h>
#include <cstddef>
#include <cstdint>

// ---------------------------------------------------------------------------
// GNN: relu(x@W_in+b); 2x SAGEConv(mean) + BN(eval) + relu; out GEMM.
// N=100000, E=1.6M, D_IN=256, H=128, D_OUT=64, fp32 in/out.
//
// R14: CSR build runs CONCURRENTLY with the input GEMM on a side stream
// (graph-capture fork-join via events). rdeg kernel removed (gather derives
// 1/deg from rowptr). GEMM/gather bodies unchanged from R13.
// ---------------------------------------------------------------------------

#define MAX_N 100000
#define MAX_E 1600000
#define HID   128

__device__ __half g_h16a[(size_t)MAX_N * HID];
__device__ __half g_h16b[(size_t)MAX_N * HID];
__device__ __half g_h16c[(size_t)MAX_N * HID];
__device__ __half g_g16 [(size_t)MAX_N * HID];
__device__ int    g_degi  [MAX_N];
__device__ int    g_cursor[MAX_N];
__device__ int    g_rowptr[MAX_N + 1];
__device__ int    g_csr   [MAX_E];
__device__ int    g_bsum  [1024];
__device__ __half g_wt[4][128 * 256];   // transposed fp16 weights per GEMM

// ---------------------------------------------------------------------------
// helpers
// ---------------------------------------------------------------------------
__device__ __forceinline__ uint32_t smem_u32(const void* p) {
    uint32_t a;
    asm("{ .reg .u64 t; cvta.to.shared.u64 t, %1; cvt.u32.u64 %0, t; }"
        : "=r"(a) : "l"(p));
    return a;
}

__device__ __forceinline__ void ldsm_x4(uint32_t* r, uint32_t addr) {
    asm volatile("ldmatrix.sync.aligned.m8n8.x4.shared.b16 {%0,%1,%2,%3}, [%4];"
                 : "=r"(r[0]), "=r"(r[1]), "=r"(r[2]), "=r"(r[3]) : "r"(addr));
}

__device__ __forceinline__ void mma_f16(float* c, const uint32_t* a, const uint32_t* b) {
    asm volatile("mma.sync.aligned.m16n8k16.row.col.f32.f16.f16.f32 "
                 "{%0,%1,%2,%3}, {%4,%5,%6,%7}, {%8,%9}, {%0,%1,%2,%3};"
                 : "+f"(c[0]), "+f"(c[1]), "+f"(c[2]), "+f"(c[3])
                 : "r"(a[0]), "r"(a[1]), "r"(a[2]), "r"(a[3]),
                   "r"(b[0]), "r"(b[1]));
}

__device__ __forceinline__ void cp16(uint32_t saddr, const void* gptr) {
    asm volatile("cp.async.ca.shared.global [%0], [%1], 16;"
                 :: "r"(saddr), "l"(gptr) : "memory");
}
__device__ __forceinline__ void cp16z(uint32_t saddr, const void* gptr, bool valid) {
    int sz = valid ? 16 : 0;
    asm volatile("cp.async.ca.shared.global [%0], [%1], 16, %2;"
                 :: "r"(saddr), "l"(gptr), "r"(sz) : "memory");
}
__device__ __forceinline__ void cp_commit() {
    asm volatile("cp.async.commit_group;" ::: "memory");
}
template<int NN>
__device__ __forceinline__ void cp_wait() {
    asm volatile("cp.async.wait_group %0;" :: "n"(NN) : "memory");
}

__device__ __forceinline__ uint32_t packh2(float a, float b) {
    __half2 t = __floats2half2_rn(a, b);
    return *reinterpret_cast<uint32_t*>(&t);
}

// ---------------------------------------------------------------------------
// CSR build
// ---------------------------------------------------------------------------
__global__ void zero_int_kernel(int* __restrict__ a, int* __restrict__ b, int n) {
    int i = blockIdx.x * blockDim.x + threadIdx.x;
    if (i < n) { a[i] = 0; b[i] = 0; }
}

__global__ void degi_kernel(const int* __restrict__ dst, int* __restrict__ deg, int E) {
    int e = blockIdx.x * blockDim.x + threadIdx.x;
    if (e < E) atomicAdd(&deg[dst[e]], 1);
}

__global__ void scan1_kernel(const int* __restrict__ deg, int* __restrict__ rowptr,
                             int* __restrict__ bsum, int n) {
    __shared__ int warp_tot[8];
    int t = threadIdx.x, lane = t & 31, wid = t >> 5;
    int base = blockIdx.x * 1024 + t * 4;
    int v0 = (base + 0 < n) ? deg[base + 0] : 0;
    int v1 = (base + 1 < n) ? deg[base + 1] : 0;
    int v2 = (base + 2 < n) ? deg[base + 2] : 0;
    int v3 = (base + 3 < n) ? deg[base + 3] : 0;
    int tot = v0 + v1 + v2 + v3;

    int inc = tot;
#pragma unroll
    for (int off = 1; off < 32; off <<= 1) {
        int y = __shfl_up_sync(0xFFFFFFFF, inc, off);
        if (lane >= off) inc += y;
    }
    if (lane == 31) warp_tot[wid] = inc;
    __syncthreads();
    if (wid == 0) {
        int w = (lane < 8) ? warp_tot[lane] : 0;
        int wi = w;
#pragma unroll
        for (int off = 1; off < 8; off <<= 1) {
            int y = __shfl_up_sync(0xFFFFFFFF, wi, off);
            if (lane >= off) wi += y;
        }
        if (lane < 8) warp_tot[lane] = wi - w;
    }
    __syncthreads();
    int excl = warp_tot[wid] + inc - tot;

    if (base + 0 < n) rowptr[base + 0] = excl;
    if (base + 1 < n) rowptr[base + 1] = excl + v0;
    if (base + 2 < n) rowptr[base + 2] = excl + v0 + v1;
    if (base + 3 < n) rowptr[base + 3] = excl + v0 + v1 + v2;
    if (t == 255) bsum[blockIdx.x] = warp_tot[7] + inc;
}

__global__ void scan2_kernel(int* __restrict__ bsum, int nblk) {
    __shared__ int sh[1024];
    int t = threadIdx.x;
#pragma unroll
    for (int i = 0; i < 4; ++i) {
        int idx = t + i * 256;
        sh[idx] = (idx < nblk) ? bsum[idx] : 0;
    }
    __syncthreads();
    for (int off = 1; off < 1024; off <<= 1) {
        int v[4];
#pragma unroll
        for (int i = 0; i < 4; ++i) {
            int idx = t + i * 256;
            v[i] = (idx >= off) ? sh[idx - off] : 0;
        }
        __syncthreads();
#pragma unroll
        for (int i = 0; i < 4; ++i) sh[t + i * 256] += v[i];
        __syncthreads();
    }
#pragma unroll
    for (int i = 0; i < 4; ++i) {
        int idx = t + i * 256;
        if (idx < nblk) bsum[idx] = (idx == 0) ? 0 : sh[idx - 1];
    }
}

__global__ void scan3_kernel(int* __restrict__ rowptr, const int* __restrict__ bsum,
                             int n, int E) {
    int i = blockIdx.x * blockDim.x + threadIdx.x;
    if (i < n) rowptr[i] += bsum[i >> 10];
    if (i == 0) rowptr[n] = E;
}

__global__ void fill_kernel(const int* __restrict__ src, const int* __restrict__ dst,
                            const int* __restrict__ rowptr, int* __restrict__ cursor,
                            int* __restrict__ csr, int E) {
    int e = blockIdx.x * blockDim.x + threadIdx.x;
    if (e >= E) return;
    int d = dst[e];
    int pos = rowptr[d] + atomicAdd(&cursor[d], 1);
    csr[pos] = src[e];
}

// ---------------------------------------------------------------------------
// Gather (fp16 in -> fp16 mean out). Warp per node, 8-edge unroll.
// 1/deg derived from rowptr (rdeg kernel removed).
// ---------------------------------------------------------------------------
__global__ void __launch_bounds__(256)
gather_kernel(const uint2* __restrict__ h2, const int* __restrict__ rowptr,
              const int* __restrict__ csr, __half* __restrict__ G, int n) {
    int gw   = (blockIdx.x * blockDim.x + threadIdx.x) >> 5;
    int lane = threadIdx.x & 31;
    if (gw >= n) return;
    int s0 = rowptr[gw], s1 = rowptr[gw + 1];
    float ax = 0.f, ay = 0.f, az = 0.f, aw = 0.f;
    int j = s0;
    for (; j + 8 <= s1; j += 8) {
        int idx[8];
        uint2 u[8];
#pragma unroll
        for (int q = 0; q < 8; ++q) idx[q] = __ldg(&csr[j + q]);
#pragma unroll
        for (int q = 0; q < 8; ++q) u[q] = h2[(size_t)idx[q] * 32 + lane];
#pragma unroll
        for (int q = 0; q < 8; ++q) {
            float2 p0 = __half22float2(*reinterpret_cast<__half2*>(&u[q].x));
            float2 p1 = __half22float2(*reinterpret_cast<__half2*>(&u[q].y));
            ax += p0.x; ay += p0.y; az += p1.x; aw += p1.y;
        }
    }
    for (; j + 4 <= s1; j += 4) {
        int idx[4];
        uint2 u[4];
#pragma unroll
        for (int q = 0; q < 4; ++q) idx[q] = __ldg(&csr[j + q]);
#pragma unroll
        for (int q = 0; q < 4; ++q) u[q] = h2[(size_t)idx[q] * 32 + lane];
#pragma unroll
        for (int q = 0; q < 4; ++q) {
            float2 p0 = __half22float2(*reinterpret_cast<__half2*>(&u[q].x));
            float2 p1 = __half22float2(*reinterpret_cast<__half2*>(&u[q].y));
            ax += p0.x; ay += p0.y; az += p1.x; aw += p1.y;
        }
    }
    for (; j < s1; ++j) {
        int i0 = __ldg(&csr[j]);
        uint2 u = h2[(size_t)i0 * 32 + lane];
        float2 p0 = __half22float2(*reinterpret_cast<__half2*>(&u.x));
        float2 p1 = __half22float2(*reinterpret_cast<__half2*>(&u.y));
        ax += p0.x; ay += p0.y; az += p1.x; aw += p1.y;
    }
    float rd = 1.0f / fmaxf((float)(s1 - s0), 1.0f);
    uint2 ov = make_uint2(packh2(ax * rd, ay * rd), packh2(az * rd, aw * rd));
    *(uint2*)(G + (size_t)gw * HID + lane * 4) = ov;
}

// ---------------------------------------------------------------------------
// Fused weight prep: all 4 GEMM weights transposed to fp16 in one launch.
// ---------------------------------------------------------------------------
__global__ void wprep_all_kernel(const float* __restrict__ w_in,
                                 const float* __restrict__ wl1,
                                 const float* __restrict__ wr1,
                                 const float* __restrict__ wl2,
                                 const float* __restrict__ wr2,
                                 const float* __restrict__ wo,
                                 __half* __restrict__ wt) {
    int i = blockIdx.x * blockDim.x + threadIdx.x;
    const float *W0, *W1; int K0, Ktot, BNw, j; __half* o;
    if (i < 32768)        { j = i;         W0 = w_in; W1 = nullptr; K0 = 256; Ktot = 256; BNw = 128; o = wt; }
    else if (i < 65536)   { j = i - 32768; W0 = wl1;  W1 = wr1;     K0 = 128; Ktot = 256; BNw = 128; o = wt + 32768; }
    else if (i < 98304)   { j = i - 65536; W0 = wl2;  W1 = wr2;     K0 = 128; Ktot = 256; BNw = 128; o = wt + 65536; }
    else if (i < 106496)  { j = i - 98304; W0 = wo;   W1 = nullptr; K0 = 128; Ktot = 128; BNw = 64;  o = wt + 98304; }
    else return;
    int n = j / Ktot, k = j % Ktot;
    float w = (k < K0) ? W0[(size_t)k * BNw + n] : W1[(size_t)(k - K0) * BNw + n];
    o[j] = __float2half_rn(w);
}

// ---------------------------------------------------------------------------
// Persistent fp16 HMMA GEMM (unchanged from R13).
// ---------------------------------------------------------------------------
template<int BN, int NC, int NC0, bool RELU, bool AFF, bool F32A, bool OUTF32>
__global__ void __launch_bounds__(256, 2)
mma_gemm_kernel(const float* __restrict__ X, int sX,
                const __half* __restrict__ A0, int sA0,
                const __half* __restrict__ A1, int sA1,
                const __half* __restrict__ W,
                const float* __restrict__ bias,
                const float* __restrict__ gamma,
                const float* __restrict__ beta,
                float* __restrict__ C,
                __half* __restrict__ H, int Nrows, int nBlocksRow)
{
    constexpr int KTOT   = NC * 32;
    constexpr int WN     = BN / 2;
    constexpr int NT8    = WN / 8;
    constexpr int NT16   = WN / 16;
    constexpr int APITCH = 80;
    constexpr int ABYTES = 128 * APITCH;
    constexpr int BPITCH = KTOT * 2 + 16;
    constexpr int BOFF   = 3 * ABYTES;
    constexpr int K8     = KTOT / 8;

    extern __shared__ __align__(128) char smem[];
    const uint32_t sbase = smem_u32(smem);
    const uint32_t bbase = sbase + BOFF;

    const int tid  = threadIdx.x;
    const int wid  = tid >> 5;
    const int lane = tid & 31;
    const int wm   = wid & 3;
    const int wn   = wid >> 2;

    // load full B once
    for (int s = tid; s < BN * K8; s += 256) {
        int n = s / K8, k8 = s % K8;
        cp16(bbase + n * BPITCH + k8 * 16, W + (size_t)n * KTOT + k8 * 8);
    }
    cp_commit();

    const int cb = wn * WN + 2 * (lane & 3);
    float2 scv[NT8], shv[NT8];
#pragma unroll
    for (int nt = 0; nt < NT8; ++nt) {
        int col = cb + nt * 8;
        float s0, h0, s1, h1;
        if constexpr (AFF) {
            s0 = __ldg(&gamma[col])     * rsqrtf(1.0f + 1e-5f);
            s1 = __ldg(&gamma[col + 1]) * rsqrtf(1.0f + 1e-5f);
            h0 = s0 * __ldg(&bias[col])     + __ldg(&beta[col]);
            h1 = s1 * __ldg(&bias[col + 1]) + __ldg(&beta[col + 1]);
        } else {
            s0 = 1.0f; s1 = 1.0f;
            h0 = __ldg(&bias[col]);
            h1 = __ldg(&bias[col + 1]);
        }
        scv[nt] = make_float2(s0, s1);
        shv[nt] = make_float2(h0, h1);
    }

    float4 af[2][2];

    auto load_tileA_f32 = [&](int row0, int c) {
#pragma unroll
        for (int s = 0; s < 2; ++s) {
            int f = tid + s * 256;
            int r = f >> 2, seg = f & 3;
            float4 v0 = make_float4(0.f, 0.f, 0.f, 0.f), v1 = v0;
            int grow = row0 + r;
            if (grow < Nrows) {
                const float* p = X + (size_t)grow * sX + c * 32 + seg * 8;
                v0 = *(const float4*)p;
                v1 = *(const float4*)(p + 4);
            }
            af[s][0] = v0; af[s][1] = v1;
        }
    };

    auto store_tileA_f16 = [&](int buf) {
        char* sp = smem + buf * ABYTES;
#pragma unroll
        for (int s = 0; s < 2; ++s) {
            int f = tid + s * 256;
            int r = f >> 2, seg = f & 3;
            uint4 v;
            v.x = packh2(af[s][0].x, af[s][0].y);
            v.y = packh2(af[s][0].z, af[s][0].w);
            v.z = packh2(af[s][1].x, af[s][1].y);
            v.w = packh2(af[s][1].z, af[s][1].w);
            *(uint4*)(sp + r * APITCH + seg * 16) = v;
        }
    };

    auto loadA_async = [&](int row0, int c, int buf) {
        const __half* Ap; int stride, koff;
        if (c < NC0) { Ap = A0; stride = sA0; koff = c * 32; }
        else         { Ap = A1; stride = sA1; koff = (c - NC0) * 32; }
        const uint32_t abase = sbase + buf * ABYTES;
#pragma unroll
        for (int s = 0; s < 2; ++s) {
            int f = tid + s * 256;
            int r = f >> 2, seg = f & 3;
            int grow = row0 + r;
            bool ok = grow < Nrows;
            size_t g = (size_t)(ok ? grow : 0) * stride + koff + seg * 8;
            cp16z(abase + r * APITCH + seg * 16, Ap + g, ok);
        }
    };

    float acc[2][NT8][4];

    auto compute = [&](int buf, int c) {
        const uint32_t aA = sbase + buf * ABYTES;
#pragma unroll
        for (int ks = 0; ks < 2; ++ks) {
            uint32_t a[2][4];
#pragma unroll
            for (int mt = 0; mt < 2; ++mt) {
                uint32_t off = (uint32_t)((wm * 32 + mt * 16 + (lane & 15)) * APITCH
                                          + (ks * 16 + (lane >> 4) * 8) * 2);
                ldsm_x4(a[mt], aA + off);
            }
#pragma unroll
            for (int nt2 = 0; nt2 < NT16; ++nt2) {
                int n_idx = wn * WN + nt2 * 16 + (lane & 7) + ((lane >> 4) & 1) * 8;
                int kg    = c * 32 + ks * 16 + ((lane >> 3) & 1) * 8;
                uint32_t b[4];
                ldsm_x4(b, bbase + (uint32_t)(n_idx * BPITCH + kg * 2));
#pragma unroll
                for (int mt = 0; mt < 2; ++mt) {
                    mma_f16(acc[mt][nt2 * 2 + 0], a[mt], b + 0);
                    mma_f16(acc[mt][nt2 * 2 + 1], a[mt], b + 2);
                }
            }
        }
    };

    for (int rb = blockIdx.x; rb < nBlocksRow; rb += gridDim.x) {
        const int row0 = rb * 128;

#pragma unroll
        for (int mt = 0; mt < 2; ++mt)
#pragma unroll
            for (int nt = 0; nt < NT8; ++nt)
#pragma unroll
                for (int q = 0; q < 4; ++q) acc[mt][nt][q] = 0.0f;

        if constexpr (!F32A) {
            loadA_async(row0, 0, 0); cp_commit();
            loadA_async(row0, 1, 1); cp_commit();
#pragma unroll
            for (int c = 0; c < NC; ++c) {
                if (c == NC - 1) cp_wait<0>(); else cp_wait<1>();
                __syncthreads();
                compute(c % 3, c);
                if (c + 2 < NC) {
                    loadA_async(row0, c + 2, (c + 2) % 3);
                    cp_commit();
                }
            }
        } else {
            cp_wait<0>();
            load_tileA_f32(row0, 0);
            store_tileA_f16(0);
            __syncthreads();
#pragma unroll
            for (int c = 0; c < NC; ++c) {
                if (c + 1 < NC) load_tileA_f32(row0, c + 1);
                compute(c & 1, c);
                if (c + 1 < NC) store_tileA_f16((c + 1) & 1);
                __syncthreads();
            }
        }

        const int rbase = row0 + wm * 32 + (lane >> 2);
#pragma unroll
        for (int mt = 0; mt < 2; ++mt) {
#pragma unroll
            for (int h = 0; h < 2; ++h) {
                int row = rbase + mt * 16 + h * 8;
                if (row >= Nrows) continue;
#pragma unroll
                for (int nt = 0; nt < NT8; ++nt) {
                    float v0 = acc[mt][nt][h * 2 + 0] * scv[nt].x + shv[nt].x;
                    float v1 = acc[mt][nt][h * 2 + 1] * scv[nt].y + shv[nt].y;
                    if constexpr (RELU) { v0 = fmaxf(v0, 0.0f); v1 = fmaxf(v1, 0.0f); }
                    size_t base = (size_t)row * BN + cb + nt * 8;
                    if constexpr (OUTF32) {
                        *(float2*)(C + base) = make_float2(v0, v1);
                    } else {
                        *(uint32_t*)(H + base) = packh2(v0, v1);
                    }
                }
            }
        }
        __syncthreads();
    }
}

// ---------------------------------------------------------------------------
// Host launcher — fork/join: CSR build overlaps wprep + input GEMM.
// ---------------------------------------------------------------------------
extern "C" void kernel_launch(void* const* d_in, const int* in_sizes, int n_in,
                              void* d_out, int out_size)
{
    const float* x     = (const float*)d_in[0];
    const int*   eidx  = (const int*)  d_in[1];
    const float* w_in  = (const float*)d_in[2];
    const float* b_in  = (const float*)d_in[3];
    const float* w_l1  = (const float*)d_in[4];
    const float* b_l1  = (const float*)d_in[5];
    const float* w_r1  = (const float*)d_in[6];
    const float* g1    = (const float*)d_in[7];
    const float* be1   = (const float*)d_in[8];
    const float* w_l2  = (const float*)d_in[9];
    const float* b_l2  = (const float*)d_in[10];
    const float* w_r2  = (const float*)d_in[11];
    const float* g2    = (const float*)d_in[12];
    const float* be2   = (const float*)d_in[13];
    const float* w_out = (const float*)d_in[14];
    const float* b_out = (const float*)d_in[15];
    float* out = (float*)d_out;

    const int N = in_sizes[0] / 256;
    const int E = in_sizes[1] / 2;
    const int* src = eidx;
    const int* dst = eidx + E;

    __half *h16a, *h16b, *h16c, *g16, *wt;
    int *degi, *cursor, *rowptr, *csr, *bsum;
    cudaGetSymbolAddress((void**)&h16a,   g_h16a);
    cudaGetSymbolAddress((void**)&h16b,   g_h16b);
    cudaGetSymbolAddress((void**)&h16c,   g_h16c);
    cudaGetSymbolAddress((void**)&g16,    g_g16);
    cudaGetSymbolAddress((void**)&degi,   g_degi);
    cudaGetSymbolAddress((void**)&cursor, g_cursor);
    cudaGetSymbolAddress((void**)&rowptr, g_rowptr);
    cudaGetSymbolAddress((void**)&csr,    g_csr);
    cudaGetSymbolAddress((void**)&bsum,   g_bsum);
    cudaGetSymbolAddress((void**)&wt,     g_wt);
    const int WSTR = 128 * 256;

    const int nBlocks    = (N + 255) / 256;
    const int eBlocks    = (E + 255) / 256;
    const int rowBlocks  = (N + 127) / 128;
    const int gemmGrid   = 304;
    const int scanBlocks = (N + 1023) / 1024;
    const int gatherBlocks = (int)(((long long)N * 32 + 255) / 256);

    const int S256 = 3 * (128 * 80) + 128 * (256 * 2 + 16);   // 98304
    const int S64  = 3 * (128 * 80) + 64  * (128 * 2 + 16);   // 48128
    cudaFuncSetAttribute(mma_gemm_kernel<128, 8, 8, true,  false, true,  false>,
                         cudaFuncAttributeMaxDynamicSharedMemorySize, S256);
    cudaFuncSetAttribute(mma_gemm_kernel<128, 8, 4, true,  true,  false, false>,
                         cudaFuncAttributeMaxDynamicSharedMemorySize, S256);
    cudaFuncSetAttribute(mma_gemm_kernel<64,  4, 4, false, false, false, true >,
                         cudaFuncAttributeMaxDynamicSharedMemorySize, S64);

    // lazy side-stream + events (created on first, uncaptured call; no device mem)
    static cudaStream_t s2 = nullptr;
    static cudaEvent_t  e1 = nullptr, e2 = nullptr;
    if (s2 == nullptr) {
        cudaStreamCreateWithFlags(&s2, cudaStreamNonBlocking);
        cudaEventCreateWithFlags(&e1, cudaEventDisableTiming);
        cudaEventCreateWithFlags(&e2, cudaEventDisableTiming);
    }

    // ---- fork: CSR chain on s2, concurrent with wprep + input GEMM ----
    cudaEventRecord(e1, 0);
    cudaStreamWaitEvent(s2, e1, 0);

    zero_int_kernel<<<nBlocks, 256, 0, s2>>>(degi, cursor, N);
    degi_kernel<<<eBlocks, 256, 0, s2>>>(dst, degi, E);
    scan1_kernel<<<scanBlocks, 256, 0, s2>>>(degi, rowptr, bsum, N);
    scan2_kernel<<<1, 256, 0, s2>>>(bsum, scanBlocks);
    scan3_kernel<<<nBlocks, 256, 0, s2>>>(rowptr, bsum, N, E);
    fill_kernel<<<eBlocks, 256, 0, s2>>>(src, dst, rowptr, cursor, csr, E);
    cudaEventRecord(e2, s2);

    // main stream: weights + input GEMM
    wprep_all_kernel<<<(106496 + 255) / 256, 256>>>(w_in, w_l1, w_r1,
                                                    w_l2, w_r2, w_out, wt);
    mma_gemm_kernel<128, 8, 8, true, false, true, false>
        <<<gemmGrid, 256, S256>>>(
        x, 256, nullptr, 0, nullptr, 0, wt + 0 * WSTR,
        b_in, nullptr, nullptr, nullptr, h16a, N, rowBlocks);

    // ---- join: gather needs CSR ----
    cudaStreamWaitEvent(0, e2, 0);

    // SAGE layer 1
    gather_kernel<<<gatherBlocks, 256>>>((const uint2*)h16a, rowptr, csr, g16, N);
    mma_gemm_kernel<128, 8, 4, true, true, false, false>
        <<<gemmGrid, 256, S256>>>(
        nullptr, 0, g16, 128, h16a, 128, wt + 1 * WSTR,
        b_l1, g1, be1, nullptr, h16b, N, rowBlocks);

    // SAGE layer 2
    gather_kernel<<<gatherBlocks, 256>>>((const uint2*)h16b, rowptr, csr, g16, N);
    mma_gemm_kernel<128, 8, 4, true, true, false, false>
        <<<gemmGrid, 256, S256>>>(
        nullptr, 0, g16, 128, h16b, 128, wt + 2 * WSTR,
        b_l2, g2, be2, nullptr, h16c, N, rowBlocks);

    // output layer
    mma_gemm_kernel<64, 4, 4, false, false, false, true>
        <<<gemmGrid, 256, S64>>>(
        nullptr, 0, h16c, 128, nullptr, 0, wt + 3 * WSTR,
        b_out, nullptr, nullptr, out, nullptr, N, rowBlocks);
}